// round 2
// baseline (speedup 1.0000x reference)
#include <cuda_runtime.h>
#include <math.h>

// ---------------- problem constants ----------------
#define Dm   1024
#define Hh   16
#define DH   64
#define DFF  4096
#define DC   768
#define Tt   2048
#define Bb   2
#define Cc   77
#define MX   4096          // Bb*Tt rows of x

// ---------------- scratch (static device arrays; no allocs) ----------------
__device__ float g_ln   [(size_t)MX * Dm];          // 16 MB, reused for ln1/ln2/ln3
__device__ float g_qkv  [(size_t)MX * 3 * Dm];      // 48 MB
__device__ float g_scores[(size_t)Bb * Hh * Tt * Tt]; // 1 GB
__device__ float g_attn [(size_t)MX * Dm];          // attn out (SA, then CA)
__device__ float g_x1   [(size_t)MX * Dm];
__device__ float g_x2   [(size_t)MX * Dm];
__device__ float g_qca  [(size_t)MX * Dm];
__device__ float g_kvca [(size_t)Bb * Cc * 2 * Dm];
__device__ float g_csc  [(size_t)Bb * Hh * Tt * Cc]; // ~20 MB
__device__ float g_ff   [(size_t)MX * DFF];         // 64 MB

// ---------------- reductions ----------------
__device__ __forceinline__ float block_sum(float v, float* sh) {
    #pragma unroll
    for (int o = 16; o > 0; o >>= 1) v += __shfl_xor_sync(0xffffffffu, v, o);
    int w = threadIdx.x >> 5;
    if ((threadIdx.x & 31) == 0) sh[w] = v;
    __syncthreads();
    if (threadIdx.x < 32) {
        float t = (threadIdx.x < 8) ? sh[threadIdx.x] : 0.f;
        #pragma unroll
        for (int o = 4; o > 0; o >>= 1) t += __shfl_xor_sync(0xffffffffu, t, o);
        if (threadIdx.x == 0) sh[0] = t;
    }
    __syncthreads();
    float r = sh[0];
    __syncthreads();
    return r;
}

__device__ __forceinline__ float block_max(float v, float* sh) {
    #pragma unroll
    for (int o = 16; o > 0; o >>= 1) v = fmaxf(v, __shfl_xor_sync(0xffffffffu, v, o));
    int w = threadIdx.x >> 5;
    if ((threadIdx.x & 31) == 0) sh[w] = v;
    __syncthreads();
    if (threadIdx.x < 32) {
        float t = (threadIdx.x < 8) ? sh[threadIdx.x] : -3.0e38f;
        #pragma unroll
        for (int o = 4; o > 0; o >>= 1) t = fmaxf(t, __shfl_xor_sync(0xffffffffu, t, o));
        if (threadIdx.x == 0) sh[0] = t;
    }
    __syncthreads();
    float r = sh[0];
    __syncthreads();
    return r;
}

// ---------------- LayerNorm: one block per row, 256 thr, D=1024 ----------------
__global__ __launch_bounds__(256) void ln_kernel(
    const float* __restrict__ x, const float* __restrict__ g,
    const float* __restrict__ b, float* __restrict__ out)
{
    __shared__ float sh[8];
    long row = blockIdx.x;
    const float4* xr = (const float4*)(x + row * Dm);
    int tid = threadIdx.x;
    float4 v = xr[tid];
    float s = v.x + v.y + v.z + v.w;
    s = block_sum(s, sh);
    float mean = s * (1.0f / Dm);
    float dx = v.x - mean, dy = v.y - mean, dz = v.z - mean, dw = v.w - mean;
    float s2 = dx*dx + dy*dy + dz*dz + dw*dw;
    s2 = block_sum(s2, sh);
    float rstd = rsqrtf(s2 * (1.0f / Dm) + 1e-5f);
    float4 gg = ((const float4*)g)[tid];
    float4 bbv = ((const float4*)b)[tid];
    float4 o;
    o.x = dx * rstd * gg.x + bbv.x;
    o.y = dy * rstd * gg.y + bbv.y;
    o.z = dz * rstd * gg.z + bbv.z;
    o.w = dw * rstd * gg.w + bbv.w;
    ((float4*)(out + row * Dm))[tid] = o;
}

// ---------------- row softmax (optionally causal), in place ----------------
__global__ __launch_bounds__(256) void softmax_kernel(
    float* __restrict__ S, int L, int Trows, int causal)
{
    __shared__ float sh[8];
    int row = blockIdx.x;
    float* sr = S + (long)row * L;
    int t = row % Trows;
    int valid = causal ? (t + 1) : L;
    int tid = threadIdx.x;

    float m = -3.0e38f;
    for (int j = tid; j < valid; j += 256) m = fmaxf(m, sr[j]);
    m = block_max(m, sh);

    float sum = 0.f;
    for (int j = tid; j < valid; j += 256) {
        float e = __expf(sr[j] - m);
        sr[j] = e;
        sum += e;
    }
    sum = block_sum(sum, sh);
    float inv = 1.0f / sum;

    for (int j = tid; j < L; j += 256) {
        if (j < valid) sr[j] *= inv;
        else           sr[j] = 0.f;
    }
}

// ---------------- generic batched SGEMM with fused epilogue ----------------
// C[r,c] = epi( alpha * sum_k A[r,k]*B[k,c] )
// EPI bits: 1=+bias[c], 4=GELU(exact), 2=+Res[r*ldc+c]
// batch z -> (bb = z/Hn, hh = z%Hn); per-matrix offsets bb*s?b + hh*s?h
#define BM 128
#define BN 128
#define BKk 8
#define TMm 8
#define TNn 8

template<int EPI, bool TRB>
__global__ __launch_bounds__(256) void gemm_kernel(
    const float* __restrict__ A, const float* __restrict__ Bm,
    const float* __restrict__ bias, const float* __restrict__ Res,
    float* __restrict__ C,
    int M, int N, int K, int lda, int ldb, int ldc,
    long sAb, long sAh, long sBb, long sBh, long sCb, long sCh,
    int Hn, float alpha)
{
    __shared__ float As[BKk][BM];
    __shared__ float Bs[BKk][BN];

    int z = blockIdx.z;
    int zb = z / Hn, zh = z - zb * Hn;
    A  += zb * sAb + zh * sAh;
    Bm += zb * sBb + zh * sBh;
    C  += zb * sCb + zh * sCh;

    int tid = threadIdx.x;
    int tx = tid & 15, ty = tid >> 4;
    int row0 = blockIdx.y * BM, col0 = blockIdx.x * BN;

    int arow = tid >> 1;        // 0..127
    int ak0  = (tid & 1) * 4;   // 0 or 4
    int brow = tid >> 5;        // 0..7
    int bn0  = (tid & 31) * 4;  // 0..124

    float acc[TMm][TNn];
    #pragma unroll
    for (int i = 0; i < TMm; i++)
        #pragma unroll
        for (int j = 0; j < TNn; j++) acc[i][j] = 0.f;

    for (int k0 = 0; k0 < K; k0 += BKk) {
        int gr = row0 + arow;
        #pragma unroll
        for (int i = 0; i < 4; i++) {
            int gk = k0 + ak0 + i;
            float v = 0.f;
            if (gr < M && gk < K) v = A[(long)gr * lda + gk];
            As[ak0 + i][arow] = v;
        }
        {
            int gk = k0 + brow;
            #pragma unroll
            for (int i = 0; i < 4; i++) {
                int gn = col0 + bn0 + i;
                float v = 0.f;
                if (gk < K && gn < N)
                    v = TRB ? Bm[(long)gn * ldb + gk] : Bm[(long)gk * ldb + gn];
                Bs[brow][bn0 + i] = v;
            }
        }
        __syncthreads();

        #pragma unroll
        for (int kk = 0; kk < BKk; kk++) {
            float a[TMm], bfrag[TNn];
            float4 t0 = *(const float4*)&As[kk][ty * TMm];
            float4 t1 = *(const float4*)&As[kk][ty * TMm + 4];
            a[0]=t0.x; a[1]=t0.y; a[2]=t0.z; a[3]=t0.w;
            a[4]=t1.x; a[5]=t1.y; a[6]=t1.z; a[7]=t1.w;
            float4 u0 = *(const float4*)&Bs[kk][tx * TNn];
            float4 u1 = *(const float4*)&Bs[kk][tx * TNn + 4];
            bfrag[0]=u0.x; bfrag[1]=u0.y; bfrag[2]=u0.z; bfrag[3]=u0.w;
            bfrag[4]=u1.x; bfrag[5]=u1.y; bfrag[6]=u1.z; bfrag[7]=u1.w;
            #pragma unroll
            for (int i = 0; i < TMm; i++)
                #pragma unroll
                for (int j = 0; j < TNn; j++)
                    acc[i][j] += a[i] * bfrag[j];
        }
        __syncthreads();
    }

    #pragma unroll
    for (int i = 0; i < TMm; i++) {
        int r = row0 + ty * TMm + i;
        if (r >= M) continue;
        #pragma unroll
        for (int j = 0; j < TNn; j++) {
            int c = col0 + tx * TNn + j;
            if (c >= N) continue;
            float v = acc[i][j] * alpha;
            if (EPI & 1) v += bias[c];
            if (EPI & 4) v = 0.5f * v * (1.0f + erff(v * 0.70710678118654752f));
            if (EPI & 2) v += Res[(long)r * ldc + c];
            C[(long)r * ldc + c] = v;
        }
    }
}

// ---------------- host side ----------------
static inline dim3 ggrid(int M, int N, int Z) {
    return dim3((unsigned)((N + BN - 1) / BN), (unsigned)((M + BM - 1) / BM), (unsigned)Z);
}

extern "C" void kernel_launch(void* const* d_in, const int* in_sizes, int n_in,
                              void* d_out, int out_size)
{
    const float* x        = (const float*)d_in[0];
    const float* cond     = (const float*)d_in[1];
    const float* Wqkv     = (const float*)d_in[2];
    const float* Wproj_sa = (const float*)d_in[3];
    const float* bproj_sa = (const float*)d_in[4];
    const float* g1       = (const float*)d_in[5];
    const float* b1       = (const float*)d_in[6];
    const float* Wq_ca    = (const float*)d_in[7];
    const float* Wkv_ca   = (const float*)d_in[8];
    const float* Wproj_ca = (const float*)d_in[9];
    const float* bproj_ca = (const float*)d_in[10];
    const float* g2       = (const float*)d_in[11];
    const float* b2       = (const float*)d_in[12];
    const float* Wff1     = (const float*)d_in[13];
    const float* bff1     = (const float*)d_in[14];
    const float* Wff2     = (const float*)d_in[15];
    const float* bff2     = (const float*)d_in[16];
    const float* g3       = (const float*)d_in[17];
    const float* b3       = (const float*)d_in[18];
    float* out            = (float*)d_out;

    float *p_ln, *p_qkv, *p_sc, *p_attn, *p_x1, *p_x2, *p_qca, *p_kvca, *p_csc, *p_ff;
    cudaGetSymbolAddress((void**)&p_ln,   g_ln);
    cudaGetSymbolAddress((void**)&p_qkv,  g_qkv);
    cudaGetSymbolAddress((void**)&p_sc,   g_scores);
    cudaGetSymbolAddress((void**)&p_attn, g_attn);
    cudaGetSymbolAddress((void**)&p_x1,   g_x1);
    cudaGetSymbolAddress((void**)&p_x2,   g_x2);
    cudaGetSymbolAddress((void**)&p_qca,  g_qca);
    cudaGetSymbolAddress((void**)&p_kvca, g_kvca);
    cudaGetSymbolAddress((void**)&p_csc,  g_csc);
    cudaGetSymbolAddress((void**)&p_ff,   g_ff);

    const long T3D = (long)Tt * 3 * Dm;     // qkv batch-b stride
    const long TT  = (long)Tt * Tt;
    const long HTT = (long)Hh * TT;
    const long TD  = (long)Tt * Dm;
    const long KVb = (long)Cc * 2 * Dm;     // kv_ca batch-b stride
    const long TC  = (long)Tt * Cc;
    const long HTC = (long)Hh * TC;
    const float iscale = 0.125f;            // DH^-0.5

    // ---- 1) ln1 = LN(x)
    ln_kernel<<<MX, 256>>>(x, g1, b1, p_ln);

    // ---- 2) qkv = ln1 @ Wqkv
    gemm_kernel<0,false><<<ggrid(MX, 3*Dm, 1), 256>>>(
        p_ln, Wqkv, nullptr, nullptr, p_qkv,
        MX, 3*Dm, Dm, Dm, 3*Dm, 3*Dm, 0,0,0,0,0,0, 1, 1.0f);

    // ---- 3) S = scale * Q @ K^T   (batched over b,h)
    gemm_kernel<0,true><<<ggrid(Tt, Tt, Bb*Hh), 256>>>(
        p_qkv, p_qkv + Dm, nullptr, nullptr, p_sc,
        Tt, Tt, DH, 3*Dm, 3*Dm, Tt,
        T3D, DH, T3D, DH, HTT, TT, Hh, iscale);

    // ---- 4) causal softmax rows
    softmax_kernel<<<Bb*Hh*Tt, 256>>>(p_sc, Tt, Tt, 1);

    // ---- 5) attn = P @ V
    gemm_kernel<0,false><<<ggrid(Tt, DH, Bb*Hh), 256>>>(
        p_sc, p_qkv + 2*Dm, nullptr, nullptr, p_attn,
        Tt, DH, Tt, Tt, 3*Dm, Dm,
        HTT, TT, T3D, DH, TD, DH, Hh, 1.0f);

    // ---- 6) x1 = x + attn @ Wproj_sa + bproj_sa
    gemm_kernel<3,false><<<ggrid(MX, Dm, 1), 256>>>(
        p_attn, Wproj_sa, bproj_sa, x, p_x1,
        MX, Dm, Dm, Dm, Dm, Dm, 0,0,0,0,0,0, 1, 1.0f);

    // ---- 7) ln2 = LN(x1)
    ln_kernel<<<MX, 256>>>(p_x1, g2, b2, p_ln);

    // ---- 8) q_ca = ln2 @ Wq_ca
    gemm_kernel<0,false><<<ggrid(MX, Dm, 1), 256>>>(
        p_ln, Wq_ca, nullptr, nullptr, p_qca,
        MX, Dm, Dm, Dm, Dm, Dm, 0,0,0,0,0,0, 1, 1.0f);

    // ---- 9) kv_ca = cond @ Wkv_ca   (flattened (B*C, DC))
    gemm_kernel<0,false><<<ggrid(Bb*Cc, 2*Dm, 1), 256>>>(
        cond, Wkv_ca, nullptr, nullptr, p_kvca,
        Bb*Cc, 2*Dm, DC, DC, 2*Dm, 2*Dm, 0,0,0,0,0,0, 1, 1.0f);

    // ---- 10) Sc = scale * Qca @ Kca^T
    gemm_kernel<0,true><<<ggrid(Tt, Cc, Bb*Hh), 256>>>(
        p_qca, p_kvca, nullptr, nullptr, p_csc,
        Tt, Cc, DH, Dm, 2*Dm, Cc,
        TD, DH, KVb, DH, HTC, TC, Hh, iscale);

    // ---- 11) softmax (non-causal, L=77)
    softmax_kernel<<<Bb*Hh*Tt, 256>>>(p_csc, Cc, Tt, 0);

    // ---- 12) ca_out = Pc @ Vca   (reuse p_attn)
    gemm_kernel<0,false><<<ggrid(Tt, DH, Bb*Hh), 256>>>(
        p_csc, p_kvca + Dm, nullptr, nullptr, p_attn,
        Tt, DH, Cc, Cc, 2*Dm, Dm,
        HTC, TC, KVb, DH, TD, DH, Hh, 1.0f);

    // ---- 13) x2 = x1 + ca_out @ Wproj_ca + bproj_ca
    gemm_kernel<3,false><<<ggrid(MX, Dm, 1), 256>>>(
        p_attn, Wproj_ca, bproj_ca, p_x1, p_x2,
        MX, Dm, Dm, Dm, Dm, Dm, 0,0,0,0,0,0, 1, 1.0f);

    // ---- 14) ln3 = LN(x2)
    ln_kernel<<<MX, 256>>>(p_x2, g3, b3, p_ln);

    // ---- 15) ffh = gelu(ln3 @ Wff1 + bff1)
    gemm_kernel<5,false><<<ggrid(MX, DFF, 1), 256>>>(
        p_ln, Wff1, bff1, nullptr, p_ff,
        MX, DFF, Dm, Dm, DFF, DFF, 0,0,0,0,0,0, 1, 1.0f);

    // ---- 16) out = x2 + ffh @ Wff2 + bff2
    gemm_kernel<3,false><<<ggrid(MX, Dm, 1), 256>>>(
        p_ff, Wff2, bff2, p_x2, out,
        MX, Dm, DFF, DFF, Dm, Dm, 0,0,0,0,0,0, 1, 1.0f);
}

// round 3
// speedup vs baseline: 3.5729x; 3.5729x over previous
#include <cuda_runtime.h>
#include <math.h>

// ---------------- problem constants ----------------
#define Dm   1024
#define Hh   16
#define DH   64
#define DFF  4096
#define DC   768
#define Tt   2048
#define Bb   2
#define Cc   77
#define MX   4096          // Bb*Tt rows of x

// ---------------- scratch (static device arrays; no allocs) ----------------
__device__ float g_ln   [(size_t)MX * Dm];
__device__ float g_qkv  [(size_t)MX * 3 * Dm];
__device__ float g_scores[(size_t)Bb * Hh * Tt * Tt];
__device__ float g_attn [(size_t)MX * Dm];
__device__ float g_x1   [(size_t)MX * Dm];
__device__ float g_x2   [(size_t)MX * Dm];
__device__ float g_qca  [(size_t)MX * Dm];
__device__ float g_kvca [(size_t)Bb * Cc * 2 * Dm];
__device__ float g_csc  [(size_t)Bb * Hh * Tt * Cc];
__device__ float g_ff   [(size_t)MX * DFF];

// ---------------- reductions ----------------
__device__ __forceinline__ float block_sum(float v, float* sh) {
    #pragma unroll
    for (int o = 16; o > 0; o >>= 1) v += __shfl_xor_sync(0xffffffffu, v, o);
    int w = threadIdx.x >> 5;
    if ((threadIdx.x & 31) == 0) sh[w] = v;
    __syncthreads();
    if (threadIdx.x < 32) {
        float t = (threadIdx.x < 8) ? sh[threadIdx.x] : 0.f;
        #pragma unroll
        for (int o = 4; o > 0; o >>= 1) t += __shfl_xor_sync(0xffffffffu, t, o);
        if (threadIdx.x == 0) sh[0] = t;
    }
    __syncthreads();
    float r = sh[0];
    __syncthreads();
    return r;
}

__device__ __forceinline__ float block_max(float v, float* sh) {
    #pragma unroll
    for (int o = 16; o > 0; o >>= 1) v = fmaxf(v, __shfl_xor_sync(0xffffffffu, v, o));
    int w = threadIdx.x >> 5;
    if ((threadIdx.x & 31) == 0) sh[w] = v;
    __syncthreads();
    if (threadIdx.x < 32) {
        float t = (threadIdx.x < 8) ? sh[threadIdx.x] : -3.0e38f;
        #pragma unroll
        for (int o = 4; o > 0; o >>= 1) t = fmaxf(t, __shfl_xor_sync(0xffffffffu, t, o));
        if (threadIdx.x == 0) sh[0] = t;
    }
    __syncthreads();
    float r = sh[0];
    __syncthreads();
    return r;
}

// ---------------- LayerNorm ----------------
__global__ __launch_bounds__(256) void ln_kernel(
    const float* __restrict__ x, const float* __restrict__ g,
    const float* __restrict__ b, float* __restrict__ out)
{
    __shared__ float sh[8];
    long row = blockIdx.x;
    const float4* xr = (const float4*)(x + row * Dm);
    int tid = threadIdx.x;
    float4 v = xr[tid];
    float s = v.x + v.y + v.z + v.w;
    s = block_sum(s, sh);
    float mean = s * (1.0f / Dm);
    float dx = v.x - mean, dy = v.y - mean, dz = v.z - mean, dw = v.w - mean;
    float s2 = dx*dx + dy*dy + dz*dz + dw*dw;
    s2 = block_sum(s2, sh);
    float rstd = rsqrtf(s2 * (1.0f / Dm) + 1e-5f);
    float4 gg = ((const float4*)g)[tid];
    float4 bbv = ((const float4*)b)[tid];
    float4 o;
    o.x = dx * rstd * gg.x + bbv.x;
    o.y = dy * rstd * gg.y + bbv.y;
    o.z = dz * rstd * gg.z + bbv.z;
    o.w = dw * rstd * gg.w + bbv.w;
    ((float4*)(out + row * Dm))[tid] = o;
}

// ---------------- row softmax (optionally causal), in place ----------------
__global__ __launch_bounds__(256) void softmax_kernel(
    float* __restrict__ S, int L, int Trows, int causal)
{
    __shared__ float sh[8];
    int row = blockIdx.x;
    float* sr = S + (long)row * L;
    int t = row % Trows;
    int valid = causal ? (t + 1) : L;
    int tid = threadIdx.x;

    float m = -3.0e38f;
    for (int j = tid; j < valid; j += 256) m = fmaxf(m, sr[j]);
    m = block_max(m, sh);

    float sum = 0.f;
    for (int j = tid; j < valid; j += 256) {
        float e = __expf(sr[j] - m);
        sr[j] = e;
        sum += e;
    }
    sum = block_sum(sum, sh);
    float inv = 1.0f / sum;

    for (int j = tid; j < L; j += 256) {
        if (j < valid) sr[j] *= inv;
        else           sr[j] = 0.f;
    }
}

// ================= tf32 tensor-core batched GEMM =================
// C = epi( alpha * A @ B ), A row-major [M,K]; B row-major [K,N] or (TRB) [N,K].
// EPI bits: 1=+bias[c], 4=GELU(exact), 2=+Res.
// mode: 0 normal, 1 = causal upper-block skip (QK^T), 2 = causal K-limit (P@V)
#define BM 128
#define BN 128
#define BK 16
#define SAS 20     // A smem row stride ([m][k])
#define SBS 136    // B smem row stride ([k][n])

__device__ __forceinline__ unsigned totf(float f) {
    unsigned u;
    asm("cvt.rna.tf32.f32 %0, %1;" : "=r"(u) : "f"(f));
    return u;
}

__device__ __forceinline__ void mma_tf32(float c[4],
    unsigned a0, unsigned a1, unsigned a2, unsigned a3,
    unsigned b0, unsigned b1)
{
    asm volatile(
        "mma.sync.aligned.m16n8k8.row.col.f32.tf32.tf32.f32 "
        "{%0,%1,%2,%3}, {%4,%5,%6,%7}, {%8,%9}, {%0,%1,%2,%3};\n"
        : "+f"(c[0]), "+f"(c[1]), "+f"(c[2]), "+f"(c[3])
        : "r"(a0), "r"(a1), "r"(a2), "r"(a3), "r"(b0), "r"(b1));
}

template<int EPI, bool TRB>
__global__ __launch_bounds__(256, 2) void tgemm(
    const float* __restrict__ A, const float* __restrict__ Bm,
    const float* __restrict__ bias, const float* __restrict__ Res,
    float* __restrict__ C,
    int M, int N, int K, int lda, int ldb, int ldc,
    long sAb, long sAh, long sBb, long sBh, long sCb, long sCh,
    int Hn, float alpha, int mode)
{
    __shared__ unsigned As[2][BM * SAS];   // [m][k]
    __shared__ unsigned Bs[2][BM * SAS];   // non-TRB: [k][n] stride SBS (BK*SBS<=BM*SAS); TRB: [n][k] stride SAS

    int z = blockIdx.z;
    int zb = z / Hn, zh = z - zb * Hn;
    A  += zb * sAb + zh * sAh;
    Bm += zb * sBb + zh * sBh;
    C  += zb * sCb + zh * sCh;

    int row0 = blockIdx.y * BM, col0 = blockIdx.x * BN;
    if (mode == 1 && col0 >= row0 + BM) return;   // fully-masked causal block
    int Keff = (mode == 2) ? min(K, row0 + BM) : K;

    int tid  = threadIdx.x;
    int lane = tid & 31, warp = tid >> 5;
    int wm = (warp & 1) * 64;
    int wn = (warp >> 1) * 32;
    int gid = lane >> 2, tg = lane & 3;

    float acc[4][4][4];
    #pragma unroll
    for (int i = 0; i < 4; i++)
        #pragma unroll
        for (int j = 0; j < 4; j++)
            #pragma unroll
            for (int r = 0; r < 4; r++) acc[i][j][r] = 0.f;

    const bool vecA = ((lda & 3) == 0) && ((K & 3) == 0);
    const bool vecBt = ((ldb & 3) == 0) && ((K & 3) == 0);
    const bool vecBn = ((ldb & 3) == 0);

    float va[2][4], vb[2][4];

    // ---- loaders into registers ----
    auto ldAreg = [&](int k0) {
        #pragma unroll
        for (int it = 0; it < 2; it++) {
            int idx = it * 256 + tid;
            int row = idx >> 2, kq = (idx & 3) * 4;
            int gr = row0 + row, gk = k0 + kq;
            if (vecA) {
                if (gr < M && gk < K) {
                    float4 t = *(const float4*)(A + (long)gr * lda + gk);
                    va[it][0] = t.x; va[it][1] = t.y; va[it][2] = t.z; va[it][3] = t.w;
                } else { va[it][0]=va[it][1]=va[it][2]=va[it][3]=0.f; }
            } else {
                #pragma unroll
                for (int j = 0; j < 4; j++)
                    va[it][j] = (gr < M && gk + j < K) ? A[(long)gr * lda + gk + j] : 0.f;
            }
        }
    };
    auto ldBreg = [&](int k0) {
        if (TRB) {
            #pragma unroll
            for (int it = 0; it < 2; it++) {
                int idx = it * 256 + tid;
                int row = idx >> 2, kq = (idx & 3) * 4;
                int gn = col0 + row, gk = k0 + kq;
                if (vecBt) {
                    if (gn < N && gk < K) {
                        float4 t = *(const float4*)(Bm + (long)gn * ldb + gk);
                        vb[it][0] = t.x; vb[it][1] = t.y; vb[it][2] = t.z; vb[it][3] = t.w;
                    } else { vb[it][0]=vb[it][1]=vb[it][2]=vb[it][3]=0.f; }
                } else {
                    #pragma unroll
                    for (int j = 0; j < 4; j++)
                        vb[it][j] = (gn < N && gk + j < K) ? Bm[(long)gn * ldb + gk + j] : 0.f;
                }
            }
        } else {
            #pragma unroll
            for (int it = 0; it < 2; it++) {
                int idx = it * 256 + tid;
                int k = idx >> 5, n4 = (idx & 31) * 4;
                int gk = k0 + k, gn = col0 + n4;
                if (vecBn && gn + 3 < N && gk < K) {
                    float4 t = *(const float4*)(Bm + (long)gk * ldb + gn);
                    vb[it][0] = t.x; vb[it][1] = t.y; vb[it][2] = t.z; vb[it][3] = t.w;
                } else {
                    #pragma unroll
                    for (int j = 0; j < 4; j++)
                        vb[it][j] = (gk < K && gn + j < N) ? Bm[(long)gk * ldb + gn + j] : 0.f;
                }
            }
        }
    };
    auto stTile = [&](int buf) {
        #pragma unroll
        for (int it = 0; it < 2; it++) {
            int idx = it * 256 + tid;
            int row = idx >> 2, kq = (idx & 3) * 4;
            uint4 u;
            u.x = totf(va[it][0]); u.y = totf(va[it][1]);
            u.z = totf(va[it][2]); u.w = totf(va[it][3]);
            *(uint4*)&As[buf][row * SAS + kq] = u;
        }
        if (TRB) {
            #pragma unroll
            for (int it = 0; it < 2; it++) {
                int idx = it * 256 + tid;
                int row = idx >> 2, kq = (idx & 3) * 4;
                uint4 u;
                u.x = totf(vb[it][0]); u.y = totf(vb[it][1]);
                u.z = totf(vb[it][2]); u.w = totf(vb[it][3]);
                *(uint4*)&Bs[buf][row * SAS + kq] = u;
            }
        } else {
            #pragma unroll
            for (int it = 0; it < 2; it++) {
                int idx = it * 256 + tid;
                int k = idx >> 5, n4 = (idx & 31) * 4;
                uint4 u;
                u.x = totf(vb[it][0]); u.y = totf(vb[it][1]);
                u.z = totf(vb[it][2]); u.w = totf(vb[it][3]);
                *(uint4*)&Bs[buf][k * SBS + n4] = u;
            }
        }
    };

    int ntiles = (Keff + BK - 1) / BK;

    ldAreg(0); ldBreg(0);
    stTile(0);
    __syncthreads();

    for (int t = 0; t < ntiles; t++) {
        int buf = t & 1, nbuf = buf ^ 1;
        if (t + 1 < ntiles) { ldAreg((t + 1) * BK); ldBreg((t + 1) * BK); }

        #pragma unroll
        for (int ks = 0; ks < 2; ks++) {
            int k0s = ks * 8;
            unsigned a[4][4], b[4][2];
            #pragma unroll
            for (int mi = 0; mi < 4; mi++) {
                int r = wm + mi * 16 + gid;
                a[mi][0] = As[buf][r * SAS + k0s + tg];
                a[mi][1] = As[buf][(r + 8) * SAS + k0s + tg];
                a[mi][2] = As[buf][r * SAS + k0s + tg + 4];
                a[mi][3] = As[buf][(r + 8) * SAS + k0s + tg + 4];
            }
            #pragma unroll
            for (int ni = 0; ni < 4; ni++) {
                int n = wn + ni * 8 + gid;
                if (TRB) {
                    b[ni][0] = Bs[buf][n * SAS + k0s + tg];
                    b[ni][1] = Bs[buf][n * SAS + k0s + tg + 4];
                } else {
                    b[ni][0] = Bs[buf][(k0s + tg) * SBS + n];
                    b[ni][1] = Bs[buf][(k0s + tg + 4) * SBS + n];
                }
            }
            #pragma unroll
            for (int mi = 0; mi < 4; mi++)
                #pragma unroll
                for (int ni = 0; ni < 4; ni++)
                    mma_tf32(acc[mi][ni], a[mi][0], a[mi][1], a[mi][2], a[mi][3],
                             b[ni][0], b[ni][1]);
        }

        if (t + 1 < ntiles) { stTile(nbuf); __syncthreads(); }
    }

    // ---- epilogue ----
    #pragma unroll
    for (int mi = 0; mi < 4; mi++) {
        #pragma unroll
        for (int ni = 0; ni < 4; ni++) {
            #pragma unroll
            for (int rr = 0; rr < 2; rr++) {
                int r = row0 + wm + mi * 16 + gid + rr * 8;
                if (r >= M) continue;
                #pragma unroll
                for (int cc = 0; cc < 2; cc++) {
                    int c = col0 + wn + ni * 8 + tg * 2 + cc;
                    if (c >= N) continue;
                    float v = acc[mi][ni][rr * 2 + cc] * alpha;
                    if (EPI & 1) v += bias[c];
                    if (EPI & 4) v = 0.5f * v * (1.0f + erff(v * 0.70710678118654752f));
                    if (EPI & 2) v += Res[(long)r * ldc + c];
                    C[(long)r * ldc + c] = v;
                }
            }
        }
    }
}

// ---------------- host side ----------------
static inline dim3 ggrid(int M, int N, int Z) {
    return dim3((unsigned)((N + BN - 1) / BN), (unsigned)((M + BM - 1) / BM), (unsigned)Z);
}

extern "C" void kernel_launch(void* const* d_in, const int* in_sizes, int n_in,
                              void* d_out, int out_size)
{
    const float* x        = (const float*)d_in[0];
    const float* cond     = (const float*)d_in[1];
    const float* Wqkv     = (const float*)d_in[2];
    const float* Wproj_sa = (const float*)d_in[3];
    const float* bproj_sa = (const float*)d_in[4];
    const float* g1       = (const float*)d_in[5];
    const float* b1       = (const float*)d_in[6];
    const float* Wq_ca    = (const float*)d_in[7];
    const float* Wkv_ca   = (const float*)d_in[8];
    const float* Wproj_ca = (const float*)d_in[9];
    const float* bproj_ca = (const float*)d_in[10];
    const float* g2       = (const float*)d_in[11];
    const float* b2       = (const float*)d_in[12];
    const float* Wff1     = (const float*)d_in[13];
    const float* bff1     = (const float*)d_in[14];
    const float* Wff2     = (const float*)d_in[15];
    const float* bff2     = (const float*)d_in[16];
    const float* g3       = (const float*)d_in[17];
    const float* b3       = (const float*)d_in[18];
    float* out            = (float*)d_out;

    float *p_ln, *p_qkv, *p_sc, *p_attn, *p_x1, *p_x2, *p_qca, *p_kvca, *p_csc, *p_ff;
    cudaGetSymbolAddress((void**)&p_ln,   g_ln);
    cudaGetSymbolAddress((void**)&p_qkv,  g_qkv);
    cudaGetSymbolAddress((void**)&p_sc,   g_scores);
    cudaGetSymbolAddress((void**)&p_attn, g_attn);
    cudaGetSymbolAddress((void**)&p_x1,   g_x1);
    cudaGetSymbolAddress((void**)&p_x2,   g_x2);
    cudaGetSymbolAddress((void**)&p_qca,  g_qca);
    cudaGetSymbolAddress((void**)&p_kvca, g_kvca);
    cudaGetSymbolAddress((void**)&p_csc,  g_csc);
    cudaGetSymbolAddress((void**)&p_ff,   g_ff);

    const long T3D = (long)Tt * 3 * Dm;
    const long TT  = (long)Tt * Tt;
    const long HTT = (long)Hh * TT;
    const long TD  = (long)Tt * Dm;
    const long KVb = (long)Cc * 2 * Dm;
    const long TC  = (long)Tt * Cc;
    const long HTC = (long)Hh * TC;
    const float iscale = 0.125f;

    // 1) ln1 = LN(x)
    ln_kernel<<<MX, 256>>>(x, g1, b1, p_ln);

    // 2) qkv = ln1 @ Wqkv
    tgemm<0,false><<<ggrid(MX, 3*Dm, 1), 256>>>(
        p_ln, Wqkv, nullptr, nullptr, p_qkv,
        MX, 3*Dm, Dm, Dm, 3*Dm, 3*Dm, 0,0,0,0,0,0, 1, 1.0f, 0);

    // 3) S = scale * Q @ K^T (causal: skip upper blocks)
    tgemm<0,true><<<ggrid(Tt, Tt, Bb*Hh), 256>>>(
        p_qkv, p_qkv + Dm, nullptr, nullptr, p_sc,
        Tt, Tt, DH, 3*Dm, 3*Dm, Tt,
        T3D, DH, T3D, DH, HTT, TT, Hh, iscale, 1);

    // 4) causal softmax
    softmax_kernel<<<Bb*Hh*Tt, 256>>>(p_sc, Tt, Tt, 1);

    // 5) attn = P @ V (K-loop limited to causal extent)
    tgemm<0,false><<<ggrid(Tt, DH, Bb*Hh), 256>>>(
        p_sc, p_qkv + 2*Dm, nullptr, nullptr, p_attn,
        Tt, DH, Tt, Tt, 3*Dm, Dm,
        HTT, TT, T3D, DH, TD, DH, Hh, 1.0f, 2);

    // 6) x1 = x + attn @ Wproj_sa + b
    tgemm<3,false><<<ggrid(MX, Dm, 1), 256>>>(
        p_attn, Wproj_sa, bproj_sa, x, p_x1,
        MX, Dm, Dm, Dm, Dm, Dm, 0,0,0,0,0,0, 1, 1.0f, 0);

    // 7) ln2 = LN(x1)
    ln_kernel<<<MX, 256>>>(p_x1, g2, b2, p_ln);

    // 8) q_ca = ln2 @ Wq_ca
    tgemm<0,false><<<ggrid(MX, Dm, 1), 256>>>(
        p_ln, Wq_ca, nullptr, nullptr, p_qca,
        MX, Dm, Dm, Dm, Dm, Dm, 0,0,0,0,0,0, 1, 1.0f, 0);

    // 9) kv_ca = cond @ Wkv_ca
    tgemm<0,false><<<ggrid(Bb*Cc, 2*Dm, 1), 256>>>(
        cond, Wkv_ca, nullptr, nullptr, p_kvca,
        Bb*Cc, 2*Dm, DC, DC, 2*Dm, 2*Dm, 0,0,0,0,0,0, 1, 1.0f, 0);

    // 10) Sc = scale * Qca @ Kca^T
    tgemm<0,true><<<ggrid(Tt, Cc, Bb*Hh), 256>>>(
        p_qca, p_kvca, nullptr, nullptr, p_csc,
        Tt, Cc, DH, Dm, 2*Dm, Cc,
        TD, DH, KVb, DH, HTC, TC, Hh, iscale, 0);

    // 11) softmax (L=77)
    softmax_kernel<<<Bb*Hh*Tt, 256>>>(p_csc, Cc, Tt, 0);

    // 12) ca_out = Pc @ Vca
    tgemm<0,false><<<ggrid(Tt, DH, Bb*Hh), 256>>>(
        p_csc, p_kvca + Dm, nullptr, nullptr, p_attn,
        Tt, DH, Cc, Cc, 2*Dm, Dm,
        HTC, TC, KVb, DH, TD, DH, Hh, 1.0f, 0);

    // 13) x2 = x1 + ca_out @ Wproj_ca + b
    tgemm<3,false><<<ggrid(MX, Dm, 1), 256>>>(
        p_attn, Wproj_ca, bproj_ca, p_x1, p_x2,
        MX, Dm, Dm, Dm, Dm, Dm, 0,0,0,0,0,0, 1, 1.0f, 0);

    // 14) ln3 = LN(x2)
    ln_kernel<<<MX, 256>>>(p_x2, g3, b3, p_ln);

    // 15) ffh = gelu(ln3 @ Wff1 + bff1)
    tgemm<5,false><<<ggrid(MX, DFF, 1), 256>>>(
        p_ln, Wff1, bff1, nullptr, p_ff,
        MX, DFF, Dm, Dm, DFF, DFF, 0,0,0,0,0,0, 1, 1.0f, 0);

    // 16) out = x2 + ffh @ Wff2 + bff2
    tgemm<3,false><<<ggrid(MX, Dm, 1), 256>>>(
        p_ff, Wff2, bff2, p_x2, out,
        MX, Dm, DFF, DFF, Dm, Dm, 0,0,0,0,0,0, 1, 1.0f, 0);
}

// round 4
// speedup vs baseline: 4.7774x; 1.3371x over previous
#include <cuda_runtime.h>
#include <math.h>

// ---------------- problem constants ----------------
#define Dm   1024
#define Hh   16
#define DH   64
#define DFF  4096
#define DC   768
#define Tt   2048
#define Bb   2
#define Cc   77
#define MX   4096          // Bb*Tt rows of x

// ---------------- scratch (static device arrays; no allocs) ----------------
__device__ float g_ln   [(size_t)MX * Dm];
__device__ float g_qkv  [(size_t)MX * 3 * Dm];
__device__ float g_attn [(size_t)MX * Dm];
__device__ float g_x1   [(size_t)MX * Dm];
__device__ float g_x2   [(size_t)MX * Dm];
__device__ float g_qca  [(size_t)MX * Dm];
__device__ float g_kvca [(size_t)Bb * Cc * 2 * Dm];
__device__ float g_ff   [(size_t)MX * DFF];

// ---------------- reductions ----------------
__device__ __forceinline__ float block_sum(float v, float* sh) {
    #pragma unroll
    for (int o = 16; o > 0; o >>= 1) v += __shfl_xor_sync(0xffffffffu, v, o);
    int w = threadIdx.x >> 5;
    if ((threadIdx.x & 31) == 0) sh[w] = v;
    __syncthreads();
    if (threadIdx.x < 32) {
        float t = (threadIdx.x < 8) ? sh[threadIdx.x] : 0.f;
        #pragma unroll
        for (int o = 4; o > 0; o >>= 1) t += __shfl_xor_sync(0xffffffffu, t, o);
        if (threadIdx.x == 0) sh[0] = t;
    }
    __syncthreads();
    float r = sh[0];
    __syncthreads();
    return r;
}

// ---------------- LayerNorm ----------------
__global__ __launch_bounds__(256) void ln_kernel(
    const float* __restrict__ x, const float* __restrict__ g,
    const float* __restrict__ b, float* __restrict__ out)
{
    __shared__ float sh[8];
    long row = blockIdx.x;
    const float4* xr = (const float4*)(x + row * Dm);
    int tid = threadIdx.x;
    float4 v = xr[tid];
    float s = v.x + v.y + v.z + v.w;
    s = block_sum(s, sh);
    float mean = s * (1.0f / Dm);
    float dx = v.x - mean, dy = v.y - mean, dz = v.z - mean, dw = v.w - mean;
    float s2 = dx*dx + dy*dy + dz*dz + dw*dw;
    s2 = block_sum(s2, sh);
    float rstd = rsqrtf(s2 * (1.0f / Dm) + 1e-5f);
    float4 gg = ((const float4*)g)[tid];
    float4 bbv = ((const float4*)b)[tid];
    float4 o;
    o.x = dx * rstd * gg.x + bbv.x;
    o.y = dy * rstd * gg.y + bbv.y;
    o.z = dz * rstd * gg.z + bbv.z;
    o.w = dw * rstd * gg.w + bbv.w;
    ((float4*)(out + row * Dm))[tid] = o;
}

// ---------------- tf32 helpers ----------------
__device__ __forceinline__ unsigned totf(float f) {
    unsigned u;
    asm("cvt.rna.tf32.f32 %0, %1;" : "=r"(u) : "f"(f));
    return u;
}

__device__ __forceinline__ void mma_tf32(float c[4],
    unsigned a0, unsigned a1, unsigned a2, unsigned a3,
    unsigned b0, unsigned b1)
{
    asm volatile(
        "mma.sync.aligned.m16n8k8.row.col.f32.tf32.tf32.f32 "
        "{%0,%1,%2,%3}, {%4,%5,%6,%7}, {%8,%9}, {%0,%1,%2,%3};\n"
        : "+f"(c[0]), "+f"(c[1]), "+f"(c[2]), "+f"(c[3])
        : "r"(a0), "r"(a1), "r"(a2), "r"(a3), "r"(b0), "r"(b1));
}

// ================= fused flash attention (tf32) =================
// Per block: 128 query rows of one (b,h); loops kv tiles of 64.
// 8 warps, each owns 16 q rows -> softmax rows stay inside a warp.
#define FBQ 128
#define FBK 64
#define FSQ 68      // Q/K smem row stride (words) - conflict-free frag reads
#define FSV 72      // V smem row stride - conflict-free B-frag reads
#define FSMEM ((FBQ*FSQ + FBK*FSQ + FBK*FSV) * 4)

__global__ __launch_bounds__(256, 2) void flash_kernel(
    const float* __restrict__ Qp, const float* __restrict__ Kp,
    const float* __restrict__ Vp, float* __restrict__ Op,
    int Tq, int Tk, int ldq, int ldk, int ldo,
    long sQb, long sQh, long sKb, long sKh, long sOb, long sOh,
    int Hn, float scale, int causal)
{
    extern __shared__ unsigned fsm[];
    unsigned* Qs = fsm;                     // [FBQ][FSQ]
    unsigned* Ks = fsm + FBQ * FSQ;         // [FBK][FSQ]
    unsigned* Vs = Ks + FBK * FSQ;          // [FBK][FSV]

    int z = blockIdx.z, zb = z / Hn, zh = z - zb * Hn;
    Qp += zb * sQb + zh * sQh;
    Kp += zb * sKb + zh * sKh;
    Vp += zb * sKb + zh * sKh;
    Op += zb * sOb + zh * sOh;

    int tid = threadIdx.x, lane = tid & 31, warp = tid >> 5;
    int gid = lane >> 2, tg = lane & 3;
    int row0 = blockIdx.y * FBQ;

    // ---- load Q tile (scale folded in; tf32) ----
    #pragma unroll
    for (int it = 0; it < 8; it++) {
        int idx = it * 256 + tid;           // over 2048 float4
        int r = idx >> 4, c4 = (idx & 15) * 4;
        int gr = row0 + r;
        float4 v = make_float4(0.f, 0.f, 0.f, 0.f);
        if (gr < Tq) v = *(const float4*)(Qp + (long)gr * ldq + c4);
        unsigned* q = &Qs[r * FSQ + c4];
        q[0] = totf(v.x * scale); q[1] = totf(v.y * scale);
        q[2] = totf(v.z * scale); q[3] = totf(v.w * scale);
    }

    int r_0 = row0 + warp * 16 + gid;
    int r_1 = r_0 + 8;

    float m0 = -1e30f, m1 = -1e30f, l0 = 0.f, l1 = 0.f;
    float o[8][4];
    #pragma unroll
    for (int i = 0; i < 8; i++)
        #pragma unroll
        for (int j = 0; j < 4; j++) o[i][j] = 0.f;

    int ntile = causal ? (row0 + FBQ) / FBK : (Tk + FBK - 1) / FBK;

    for (int t = 0; t < ntile; t++) {
        int kvb = t * FBK;
        __syncthreads();                    // also covers Q-store before 1st use
        // ---- load K,V tiles ----
        #pragma unroll
        for (int it = 0; it < 4; it++) {
            int idx = it * 256 + tid;       // over 1024 float4
            int r = idx >> 4, c4 = (idx & 15) * 4;
            int gr = kvb + r;
            float4 kv = make_float4(0.f,0.f,0.f,0.f), vv = make_float4(0.f,0.f,0.f,0.f);
            if (gr < Tk) {
                kv = *(const float4*)(Kp + (long)gr * ldk + c4);
                vv = *(const float4*)(Vp + (long)gr * ldk + c4);
            }
            unsigned* k = &Ks[r * FSQ + c4];
            k[0] = totf(kv.x); k[1] = totf(kv.y); k[2] = totf(kv.z); k[3] = totf(kv.w);
            unsigned* v = &Vs[r * FSV + c4];
            v[0] = totf(vv.x); v[1] = totf(vv.y); v[2] = totf(vv.z); v[3] = totf(vv.w);
        }
        __syncthreads();

        // ---- S = Q @ K^T ----
        float sacc[8][4];
        #pragma unroll
        for (int i = 0; i < 8; i++)
            #pragma unroll
            for (int j = 0; j < 4; j++) sacc[i][j] = 0.f;

        #pragma unroll
        for (int ks = 0; ks < 8; ks++) {
            int qb = (warp * 16 + gid) * FSQ + ks * 8 + tg;
            unsigned qa0 = Qs[qb];
            unsigned qa1 = Qs[qb + 8 * FSQ];
            unsigned qa2 = Qs[qb + 4];
            unsigned qa3 = Qs[qb + 8 * FSQ + 4];
            #pragma unroll
            for (int ni = 0; ni < 8; ni++) {
                int kb = (ni * 8 + gid) * FSQ + ks * 8 + tg;
                mma_tf32(sacc[ni], qa0, qa1, qa2, qa3, Ks[kb], Ks[kb + 4]);
            }
        }

        // ---- mask (only boundary tiles) ----
        bool domask = (causal && (kvb + FBK - 1 > row0)) || (kvb + FBK > Tk);
        if (domask) {
            #pragma unroll
            for (int ni = 0; ni < 8; ni++) {
                #pragma unroll
                for (int s = 0; s < 4; s++) {
                    int col = kvb + ni * 8 + tg * 2 + (s & 1);
                    int r = (s < 2) ? r_0 : r_1;
                    bool ok = (col < Tk) && (!causal || col <= r);
                    if (!ok) sacc[ni][s] = -1e30f;
                }
            }
        }

        // ---- online softmax ----
        float tm0 = -1e30f, tm1 = -1e30f;
        #pragma unroll
        for (int ni = 0; ni < 8; ni++) {
            tm0 = fmaxf(tm0, fmaxf(sacc[ni][0], sacc[ni][1]));
            tm1 = fmaxf(tm1, fmaxf(sacc[ni][2], sacc[ni][3]));
        }
        tm0 = fmaxf(tm0, __shfl_xor_sync(0xffffffffu, tm0, 1));
        tm0 = fmaxf(tm0, __shfl_xor_sync(0xffffffffu, tm0, 2));
        tm1 = fmaxf(tm1, __shfl_xor_sync(0xffffffffu, tm1, 1));
        tm1 = fmaxf(tm1, __shfl_xor_sync(0xffffffffu, tm1, 2));

        float nm0 = fmaxf(m0, tm0), nm1 = fmaxf(m1, tm1);
        float sc0 = __expf(m0 - nm0), sc1 = __expf(m1 - nm1);
        m0 = nm0; m1 = nm1;

        float rs0 = 0.f, rs1 = 0.f;
        #pragma unroll
        for (int ni = 0; ni < 8; ni++) {
            sacc[ni][0] = __expf(sacc[ni][0] - nm0); rs0 += sacc[ni][0];
            sacc[ni][1] = __expf(sacc[ni][1] - nm0); rs0 += sacc[ni][1];
            sacc[ni][2] = __expf(sacc[ni][2] - nm1); rs1 += sacc[ni][2];
            sacc[ni][3] = __expf(sacc[ni][3] - nm1); rs1 += sacc[ni][3];
        }
        rs0 += __shfl_xor_sync(0xffffffffu, rs0, 1);
        rs0 += __shfl_xor_sync(0xffffffffu, rs0, 2);
        rs1 += __shfl_xor_sync(0xffffffffu, rs1, 1);
        rs1 += __shfl_xor_sync(0xffffffffu, rs1, 2);
        l0 = l0 * sc0 + rs0;
        l1 = l1 * sc1 + rs1;

        #pragma unroll
        for (int ni = 0; ni < 8; ni++) {
            o[ni][0] *= sc0; o[ni][1] *= sc0;
            o[ni][2] *= sc1; o[ni][3] *= sc1;
        }

        // ---- O += P @ V  (A-frags built from sacc via shuffles) ----
        int bl = lane & ~3;
        int s0 = bl + (tg >> 1);
        int s1 = bl + 2 + (tg >> 1);
        bool hi = (tg & 1);
        #pragma unroll
        for (int ks = 0; ks < 8; ks++) {
            float p0 = sacc[ks][0], p1 = sacc[ks][1];
            float p2 = sacc[ks][2], p3 = sacc[ks][3];
            float v00 = __shfl_sync(0xffffffffu, p0, s0);
            float v01 = __shfl_sync(0xffffffffu, p1, s0);
            float v10 = __shfl_sync(0xffffffffu, p2, s0);
            float v11 = __shfl_sync(0xffffffffu, p3, s0);
            float w00 = __shfl_sync(0xffffffffu, p0, s1);
            float w01 = __shfl_sync(0xffffffffu, p1, s1);
            float w10 = __shfl_sync(0xffffffffu, p2, s1);
            float w11 = __shfl_sync(0xffffffffu, p3, s1);
            unsigned a0 = totf(hi ? v01 : v00);
            unsigned a1 = totf(hi ? v11 : v10);
            unsigned a2 = totf(hi ? w01 : w00);
            unsigned a3 = totf(hi ? w11 : w10);
            #pragma unroll
            for (int nj = 0; nj < 8; nj++) {
                int vb = (ks * 8 + tg) * FSV + nj * 8 + gid;
                mma_tf32(o[nj], a0, a1, a2, a3, Vs[vb], Vs[vb + 4 * FSV]);
            }
        }
    }

    // ---- normalize + write ----
    float inv0 = 1.0f / l0, inv1 = 1.0f / l1;
    #pragma unroll
    for (int nj = 0; nj < 8; nj++) {
        int c = nj * 8 + tg * 2;
        if (r_0 < Tq) {
            float2 w = make_float2(o[nj][0] * inv0, o[nj][1] * inv0);
            *(float2*)(Op + (long)r_0 * ldo + c) = w;
        }
        if (r_1 < Tq) {
            float2 w = make_float2(o[nj][2] * inv1, o[nj][3] * inv1);
            *(float2*)(Op + (long)r_1 * ldo + c) = w;
        }
    }
}

// ================= tf32 tensor-core batched GEMM =================
#define BM 128
#define BN 128
#define BK 16
#define SAS 20
#define SBS 136

template<int EPI, bool TRB>
__global__ __launch_bounds__(256, 2) void tgemm(
    const float* __restrict__ A, const float* __restrict__ Bm,
    const float* __restrict__ bias, const float* __restrict__ Res,
    float* __restrict__ C,
    int M, int N, int K, int lda, int ldb, int ldc,
    long sAb, long sAh, long sBb, long sBh, long sCb, long sCh,
    int Hn, float alpha, int mode)
{
    __shared__ unsigned As[2][BM * SAS];
    __shared__ unsigned Bs[2][BM * SAS];

    int z = blockIdx.z;
    int zb = z / Hn, zh = z - zb * Hn;
    A  += zb * sAb + zh * sAh;
    Bm += zb * sBb + zh * sBh;
    C  += zb * sCb + zh * sCh;

    int row0 = blockIdx.y * BM, col0 = blockIdx.x * BN;
    if (mode == 1 && col0 >= row0 + BM) return;
    int Keff = (mode == 2) ? min(K, row0 + BM) : K;

    int tid  = threadIdx.x;
    int lane = tid & 31, warp = tid >> 5;
    int wm = (warp & 1) * 64;
    int wn = (warp >> 1) * 32;
    int gid = lane >> 2, tg = lane & 3;

    float acc[4][4][4];
    #pragma unroll
    for (int i = 0; i < 4; i++)
        #pragma unroll
        for (int j = 0; j < 4; j++)
            #pragma unroll
            for (int r = 0; r < 4; r++) acc[i][j][r] = 0.f;

    const bool vecA = ((lda & 3) == 0) && ((K & 3) == 0);
    const bool vecBt = ((ldb & 3) == 0) && ((K & 3) == 0);
    const bool vecBn = ((ldb & 3) == 0);

    float va[2][4], vb[2][4];

    auto ldAreg = [&](int k0) {
        #pragma unroll
        for (int it = 0; it < 2; it++) {
            int idx = it * 256 + tid;
            int row = idx >> 2, kq = (idx & 3) * 4;
            int gr = row0 + row, gk = k0 + kq;
            if (vecA) {
                if (gr < M && gk < K) {
                    float4 t = *(const float4*)(A + (long)gr * lda + gk);
                    va[it][0] = t.x; va[it][1] = t.y; va[it][2] = t.z; va[it][3] = t.w;
                } else { va[it][0]=va[it][1]=va[it][2]=va[it][3]=0.f; }
            } else {
                #pragma unroll
                for (int j = 0; j < 4; j++)
                    va[it][j] = (gr < M && gk + j < K) ? A[(long)gr * lda + gk + j] : 0.f;
            }
        }
    };
    auto ldBreg = [&](int k0) {
        if (TRB) {
            #pragma unroll
            for (int it = 0; it < 2; it++) {
                int idx = it * 256 + tid;
                int row = idx >> 2, kq = (idx & 3) * 4;
                int gn = col0 + row, gk = k0 + kq;
                if (vecBt) {
                    if (gn < N && gk < K) {
                        float4 t = *(const float4*)(Bm + (long)gn * ldb + gk);
                        vb[it][0] = t.x; vb[it][1] = t.y; vb[it][2] = t.z; vb[it][3] = t.w;
                    } else { vb[it][0]=vb[it][1]=vb[it][2]=vb[it][3]=0.f; }
                } else {
                    #pragma unroll
                    for (int j = 0; j < 4; j++)
                        vb[it][j] = (gn < N && gk + j < K) ? Bm[(long)gn * ldb + gk + j] : 0.f;
                }
            }
        } else {
            #pragma unroll
            for (int it = 0; it < 2; it++) {
                int idx = it * 256 + tid;
                int k = idx >> 5, n4 = (idx & 31) * 4;
                int gk = k0 + k, gn = col0 + n4;
                if (vecBn && gn + 3 < N && gk < K) {
                    float4 t = *(const float4*)(Bm + (long)gk * ldb + gn);
                    vb[it][0] = t.x; vb[it][1] = t.y; vb[it][2] = t.z; vb[it][3] = t.w;
                } else {
                    #pragma unroll
                    for (int j = 0; j < 4; j++)
                        vb[it][j] = (gk < K && gn + j < N) ? Bm[(long)gk * ldb + gn + j] : 0.f;
                }
            }
        }
    };
    auto stTile = [&](int buf) {
        #pragma unroll
        for (int it = 0; it < 2; it++) {
            int idx = it * 256 + tid;
            int row = idx >> 2, kq = (idx & 3) * 4;
            uint4 u;
            u.x = totf(va[it][0]); u.y = totf(va[it][1]);
            u.z = totf(va[it][2]); u.w = totf(va[it][3]);
            *(uint4*)&As[buf][row * SAS + kq] = u;
        }
        if (TRB) {
            #pragma unroll
            for (int it = 0; it < 2; it++) {
                int idx = it * 256 + tid;
                int row = idx >> 2, kq = (idx & 3) * 4;
                uint4 u;
                u.x = totf(vb[it][0]); u.y = totf(vb[it][1]);
                u.z = totf(vb[it][2]); u.w = totf(vb[it][3]);
                *(uint4*)&Bs[buf][row * SAS + kq] = u;
            }
        } else {
            #pragma unroll
            for (int it = 0; it < 2; it++) {
                int idx = it * 256 + tid;
                int k = idx >> 5, n4 = (idx & 31) * 4;
                uint4 u;
                u.x = totf(vb[it][0]); u.y = totf(vb[it][1]);
                u.z = totf(vb[it][2]); u.w = totf(vb[it][3]);
                *(uint4*)&Bs[buf][k * SBS + n4] = u;
            }
        }
    };

    int ntiles = (Keff + BK - 1) / BK;

    ldAreg(0); ldBreg(0);
    stTile(0);
    __syncthreads();

    for (int t = 0; t < ntiles; t++) {
        int buf = t & 1, nbuf = buf ^ 1;
        if (t + 1 < ntiles) { ldAreg((t + 1) * BK); ldBreg((t + 1) * BK); }

        #pragma unroll
        for (int ks = 0; ks < 2; ks++) {
            int k0s = ks * 8;
            unsigned a[4][4], b[4][2];
            #pragma unroll
            for (int mi = 0; mi < 4; mi++) {
                int r = wm + mi * 16 + gid;
                a[mi][0] = As[buf][r * SAS + k0s + tg];
                a[mi][1] = As[buf][(r + 8) * SAS + k0s + tg];
                a[mi][2] = As[buf][r * SAS + k0s + tg + 4];
                a[mi][3] = As[buf][(r + 8) * SAS + k0s + tg + 4];
            }
            #pragma unroll
            for (int ni = 0; ni < 4; ni++) {
                int n = wn + ni * 8 + gid;
                if (TRB) {
                    b[ni][0] = Bs[buf][n * SAS + k0s + tg];
                    b[ni][1] = Bs[buf][n * SAS + k0s + tg + 4];
                } else {
                    b[ni][0] = Bs[buf][(k0s + tg) * SBS + n];
                    b[ni][1] = Bs[buf][(k0s + tg + 4) * SBS + n];
                }
            }
            #pragma unroll
            for (int mi = 0; mi < 4; mi++)
                #pragma unroll
                for (int ni = 0; ni < 4; ni++)
                    mma_tf32(acc[mi][ni], a[mi][0], a[mi][1], a[mi][2], a[mi][3],
                             b[ni][0], b[ni][1]);
        }

        if (t + 1 < ntiles) { stTile(nbuf); __syncthreads(); }
    }

    #pragma unroll
    for (int mi = 0; mi < 4; mi++) {
        #pragma unroll
        for (int ni = 0; ni < 4; ni++) {
            #pragma unroll
            for (int rr = 0; rr < 2; rr++) {
                int r = row0 + wm + mi * 16 + gid + rr * 8;
                if (r >= M) continue;
                #pragma unroll
                for (int cc = 0; cc < 2; cc++) {
                    int c = col0 + wn + ni * 8 + tg * 2 + cc;
                    if (c >= N) continue;
                    float v = acc[mi][ni][rr * 2 + cc] * alpha;
                    if (EPI & 1) v += bias[c];
                    if (EPI & 4) v = 0.5f * v * (1.0f + erff(v * 0.70710678118654752f));
                    if (EPI & 2) v += Res[(long)r * ldc + c];
                    C[(long)r * ldc + c] = v;
                }
            }
        }
    }
}

// ---------------- host side ----------------
static inline dim3 ggrid(int M, int N, int Z) {
    return dim3((unsigned)((N + BN - 1) / BN), (unsigned)((M + BM - 1) / BM), (unsigned)Z);
}

extern "C" void kernel_launch(void* const* d_in, const int* in_sizes, int n_in,
                              void* d_out, int out_size)
{
    const float* x        = (const float*)d_in[0];
    const float* cond     = (const float*)d_in[1];
    const float* Wqkv     = (const float*)d_in[2];
    const float* Wproj_sa = (const float*)d_in[3];
    const float* bproj_sa = (const float*)d_in[4];
    const float* g1       = (const float*)d_in[5];
    const float* b1       = (const float*)d_in[6];
    const float* Wq_ca    = (const float*)d_in[7];
    const float* Wkv_ca   = (const float*)d_in[8];
    const float* Wproj_ca = (const float*)d_in[9];
    const float* bproj_ca = (const float*)d_in[10];
    const float* g2       = (const float*)d_in[11];
    const float* b2       = (const float*)d_in[12];
    const float* Wff1     = (const float*)d_in[13];
    const float* bff1     = (const float*)d_in[14];
    const float* Wff2     = (const float*)d_in[15];
    const float* bff2     = (const float*)d_in[16];
    const float* g3       = (const float*)d_in[17];
    const float* b3       = (const float*)d_in[18];
    float* out            = (float*)d_out;

    float *p_ln, *p_qkv, *p_attn, *p_x1, *p_x2, *p_qca, *p_kvca, *p_ff;
    cudaGetSymbolAddress((void**)&p_ln,   g_ln);
    cudaGetSymbolAddress((void**)&p_qkv,  g_qkv);
    cudaGetSymbolAddress((void**)&p_attn, g_attn);
    cudaGetSymbolAddress((void**)&p_x1,   g_x1);
    cudaGetSymbolAddress((void**)&p_x2,   g_x2);
    cudaGetSymbolAddress((void**)&p_qca,  g_qca);
    cudaGetSymbolAddress((void**)&p_kvca, g_kvca);
    cudaGetSymbolAddress((void**)&p_ff,   g_ff);

    cudaFuncSetAttribute(flash_kernel, cudaFuncAttributeMaxDynamicSharedMemorySize, FSMEM);

    const long T3D = (long)Tt * 3 * Dm;
    const long TD  = (long)Tt * Dm;
    const long KVb = (long)Cc * 2 * Dm;
    const float iscale = 0.125f;

    // 1) ln1 = LN(x)
    ln_kernel<<<MX, 256>>>(x, g1, b1, p_ln);

    // 2) qkv = ln1 @ Wqkv
    tgemm<0,false><<<ggrid(MX, 3*Dm, 1), 256>>>(
        p_ln, Wqkv, nullptr, nullptr, p_qkv,
        MX, 3*Dm, Dm, Dm, 3*Dm, 3*Dm, 0,0,0,0,0,0, 1, 1.0f, 0);

    // 3) fused causal self-attention -> g_attn
    flash_kernel<<<dim3(1, Tt/FBQ, Bb*Hh), 256, FSMEM>>>(
        p_qkv, p_qkv + Dm, p_qkv + 2*Dm, p_attn,
        Tt, Tt, 3*Dm, 3*Dm, Dm,
        T3D, DH, T3D, DH, TD, DH, Hh, iscale, 1);

    // 4) x1 = x + attn @ Wproj_sa + b
    tgemm<3,false><<<ggrid(MX, Dm, 1), 256>>>(
        p_attn, Wproj_sa, bproj_sa, x, p_x1,
        MX, Dm, Dm, Dm, Dm, Dm, 0,0,0,0,0,0, 1, 1.0f, 0);

    // 5) ln2 = LN(x1)
    ln_kernel<<<MX, 256>>>(p_x1, g2, b2, p_ln);

    // 6) q_ca = ln2 @ Wq_ca
    tgemm<0,false><<<ggrid(MX, Dm, 1), 256>>>(
        p_ln, Wq_ca, nullptr, nullptr, p_qca,
        MX, Dm, Dm, Dm, Dm, Dm, 0,0,0,0,0,0, 1, 1.0f, 0);

    // 7) kv_ca = cond @ Wkv_ca
    tgemm<0,false><<<ggrid(Bb*Cc, 2*Dm, 1), 256>>>(
        cond, Wkv_ca, nullptr, nullptr, p_kvca,
        Bb*Cc, 2*Dm, DC, DC, 2*Dm, 2*Dm, 0,0,0,0,0,0, 1, 1.0f, 0);

    // 8) fused cross-attention -> g_attn
    flash_kernel<<<dim3(1, Tt/FBQ, Bb*Hh), 256, FSMEM>>>(
        p_qca, p_kvca, p_kvca + Dm, p_attn,
        Tt, Cc, Dm, 2*Dm, Dm,
        TD, DH, KVb, DH, TD, DH, Hh, iscale, 0);

    // 9) x2 = x1 + ca_out @ Wproj_ca + b
    tgemm<3,false><<<ggrid(MX, Dm, 1), 256>>>(
        p_attn, Wproj_ca, bproj_ca, p_x1, p_x2,
        MX, Dm, Dm, Dm, Dm, Dm, 0,0,0,0,0,0, 1, 1.0f, 0);

    // 10) ln3 = LN(x2)
    ln_kernel<<<MX, 256>>>(p_x2, g3, b3, p_ln);

    // 11) ffh = gelu(ln3 @ Wff1 + bff1)
    tgemm<5,false><<<ggrid(MX, DFF, 1), 256>>>(
        p_ln, Wff1, bff1, nullptr, p_ff,
        MX, DFF, Dm, Dm, DFF, DFF, 0,0,0,0,0,0, 1, 1.0f, 0);

    // 12) out = x2 + ffh @ Wff2 + bff2
    tgemm<3,false><<<ggrid(MX, Dm, 1), 256>>>(
        p_ff, Wff2, bff2, p_x2, out,
        MX, Dm, DFF, DFF, Dm, Dm, 0,0,0,0,0,0, 1, 1.0f, 0);
}

// round 5
// speedup vs baseline: 5.2353x; 1.0958x over previous
#include <cuda_runtime.h>
#include <math.h>

// ---------------- problem constants ----------------
#define Dm   1024
#define Hh   16
#define DH   64
#define DFF  4096
#define DC   768
#define Tt   2048
#define Bb   2
#define Cc   77
#define MX   4096          // Bb*Tt rows of x

// ---------------- scratch (static device arrays; no allocs) ----------------
__device__ float g_ln   [(size_t)MX * Dm];
__device__ float g_qkv  [(size_t)MX * 3 * Dm];
__device__ float g_attn [(size_t)MX * Dm];
__device__ float g_x1   [(size_t)MX * Dm];
__device__ float g_x2   [(size_t)MX * Dm];
__device__ float g_qca  [(size_t)MX * Dm];
__device__ float g_kvca [(size_t)Bb * Cc * 2 * Dm];
__device__ float g_ff   [(size_t)MX * DFF];
__device__ float g_w    [(size_t)16400000];          // tf32-rounded weights + cond

// weight-scratch offsets (floats)
#define OW_QKV   0
#define OW_PSA   (OW_QKV + Dm*3*Dm)            // 3145728
#define OW_QCA   (OW_PSA + Dm*Dm)
#define OW_KVCA  (OW_QCA + Dm*Dm)
#define OW_PCA   (OW_KVCA + DC*2*Dm)
#define OW_FF1   (OW_PCA + Dm*Dm)
#define OW_FF2   (OW_FF1 + Dm*DFF)
#define OW_COND  (OW_FF2 + DFF*Dm)
// OW_COND + Bb*Cc*DC = 16371200 <= 16400000

// ---------------- tf32 helpers ----------------
__device__ __forceinline__ unsigned totf(float f) {
    unsigned u;
    asm("cvt.rna.tf32.f32 %0, %1;" : "=r"(u) : "f"(f));
    return u;
}
__device__ __forceinline__ float totf_f(float f) { return __uint_as_float(totf(f)); }

__device__ __forceinline__ void mma_tf32(float c[4],
    unsigned a0, unsigned a1, unsigned a2, unsigned a3,
    unsigned b0, unsigned b1)
{
    asm volatile(
        "mma.sync.aligned.m16n8k8.row.col.f32.tf32.tf32.f32 "
        "{%0,%1,%2,%3}, {%4,%5,%6,%7}, {%8,%9}, {%0,%1,%2,%3};\n"
        : "+f"(c[0]), "+f"(c[1]), "+f"(c[2]), "+f"(c[3])
        : "r"(a0), "r"(a1), "r"(a2), "r"(a3), "r"(b0), "r"(b1));
}

__device__ __forceinline__ void cpa16(unsigned dst, const float* src, bool pred) {
    int sz = pred ? 16 : 0;
    asm volatile("cp.async.cg.shared.global [%0], [%1], 16, %2;\n"
                 :: "r"(dst), "l"(src), "r"(sz));
}
__device__ __forceinline__ void cpa16u(unsigned dst, const float* src) {
    asm volatile("cp.async.cg.shared.global [%0], [%1], 16;\n"
                 :: "r"(dst), "l"(src));
}
__device__ __forceinline__ void cpa_commit() {
    asm volatile("cp.async.commit_group;\n");
}
template<int N>
__device__ __forceinline__ void cpa_wait() {
    asm volatile("cp.async.wait_group %0;\n" :: "n"(N));
}

// ---------------- weight rounding prep ----------------
__global__ __launch_bounds__(256) void round_kernel(
    const float* __restrict__ src, float* __restrict__ dst, int n)
{
    int i = blockIdx.x * 256 + threadIdx.x;
    int stride = gridDim.x * 256;
    for (; i < n; i += stride) dst[i] = totf_f(src[i]);
}

// ---------------- reductions ----------------
__device__ __forceinline__ float block_sum(float v, float* sh) {
    #pragma unroll
    for (int o = 16; o > 0; o >>= 1) v += __shfl_xor_sync(0xffffffffu, v, o);
    int w = threadIdx.x >> 5;
    if ((threadIdx.x & 31) == 0) sh[w] = v;
    __syncthreads();
    if (threadIdx.x < 32) {
        float t = (threadIdx.x < 8) ? sh[threadIdx.x] : 0.f;
        #pragma unroll
        for (int o = 4; o > 0; o >>= 1) t += __shfl_xor_sync(0xffffffffu, t, o);
        if (threadIdx.x == 0) sh[0] = t;
    }
    __syncthreads();
    float r = sh[0];
    __syncthreads();
    return r;
}

// ---------------- LayerNorm (tf32-rounded output) ----------------
__global__ __launch_bounds__(256) void ln_kernel(
    const float* __restrict__ x, const float* __restrict__ g,
    const float* __restrict__ b, float* __restrict__ out)
{
    __shared__ float sh[8];
    long row = blockIdx.x;
    const float4* xr = (const float4*)(x + row * Dm);
    int tid = threadIdx.x;
    float4 v = xr[tid];
    float s = v.x + v.y + v.z + v.w;
    s = block_sum(s, sh);
    float mean = s * (1.0f / Dm);
    float dx = v.x - mean, dy = v.y - mean, dz = v.z - mean, dw = v.w - mean;
    float s2 = dx*dx + dy*dy + dz*dz + dw*dw;
    s2 = block_sum(s2, sh);
    float rstd = rsqrtf(s2 * (1.0f / Dm) + 1e-5f);
    float4 gg = ((const float4*)g)[tid];
    float4 bbv = ((const float4*)b)[tid];
    float4 o;
    o.x = totf_f(dx * rstd * gg.x + bbv.x);
    o.y = totf_f(dy * rstd * gg.y + bbv.y);
    o.z = totf_f(dz * rstd * gg.z + bbv.z);
    o.w = totf_f(dw * rstd * gg.w + bbv.w);
    ((float4*)(out + row * Dm))[tid] = o;
}

// ================= fused flash attention (tf32, pre-rounded inputs) =================
#define FBQ 128
#define FBK 64
#define FSQ 68
#define FSV 72
#define FSMEM ((FBQ*FSQ + FBK*FSQ + FBK*FSV) * 4)

__global__ __launch_bounds__(256, 2) void flash_kernel(
    const float* __restrict__ Qp, const float* __restrict__ Kp,
    const float* __restrict__ Vp, float* __restrict__ Op,
    int Tq, int Tk, int ldq, int ldk, int ldo,
    long sQb, long sQh, long sKb, long sKh, long sOb, long sOh,
    int Hn, float scale, int causal)
{
    extern __shared__ unsigned fsm[];
    unsigned* Qs = fsm;
    unsigned* Ks = fsm + FBQ * FSQ;
    unsigned* Vs = Ks + FBK * FSQ;

    int z = blockIdx.z, zb = z / Hn, zh = z - zb * Hn;
    Qp += zb * sQb + zh * sQh;
    Kp += zb * sKb + zh * sKh;
    Vp += zb * sKb + zh * sKh;
    Op += zb * sOb + zh * sOh;

    int tid = threadIdx.x, lane = tid & 31, warp = tid >> 5;
    int gid = lane >> 2, tg = lane & 3;
    int row0 = blockIdx.y * FBQ;

    // Q tile: inputs are tf32-clean; *scale (pow2) is exact
    #pragma unroll
    for (int it = 0; it < 8; it++) {
        int idx = it * 256 + tid;
        int r = idx >> 4, c4 = (idx & 15) * 4;
        int gr = row0 + r;
        float4 v = make_float4(0.f, 0.f, 0.f, 0.f);
        if (gr < Tq) v = *(const float4*)(Qp + (long)gr * ldq + c4);
        unsigned* q = &Qs[r * FSQ + c4];
        q[0] = __float_as_uint(v.x * scale); q[1] = __float_as_uint(v.y * scale);
        q[2] = __float_as_uint(v.z * scale); q[3] = __float_as_uint(v.w * scale);
    }

    int r_0 = row0 + warp * 16 + gid;
    int r_1 = r_0 + 8;

    float m0 = -1e30f, m1 = -1e30f, l0 = 0.f, l1 = 0.f;
    float o[8][4];
    #pragma unroll
    for (int i = 0; i < 8; i++)
        #pragma unroll
        for (int j = 0; j < 4; j++) o[i][j] = 0.f;

    int ntile = causal ? (row0 + FBQ) / FBK : (Tk + FBK - 1) / FBK;

    for (int t = 0; t < ntile; t++) {
        int kvb = t * FBK;
        __syncthreads();
        #pragma unroll
        for (int it = 0; it < 4; it++) {
            int idx = it * 256 + tid;
            int r = idx >> 4, c4 = (idx & 15) * 4;
            int gr = kvb + r;
            float4 kv = make_float4(0.f,0.f,0.f,0.f), vv = make_float4(0.f,0.f,0.f,0.f);
            if (gr < Tk) {
                kv = *(const float4*)(Kp + (long)gr * ldk + c4);
                vv = *(const float4*)(Vp + (long)gr * ldk + c4);
            }
            unsigned* k = &Ks[r * FSQ + c4];
            k[0] = __float_as_uint(kv.x); k[1] = __float_as_uint(kv.y);
            k[2] = __float_as_uint(kv.z); k[3] = __float_as_uint(kv.w);
            unsigned* v = &Vs[r * FSV + c4];
            v[0] = __float_as_uint(vv.x); v[1] = __float_as_uint(vv.y);
            v[2] = __float_as_uint(vv.z); v[3] = __float_as_uint(vv.w);
        }
        __syncthreads();

        float sacc[8][4];
        #pragma unroll
        for (int i = 0; i < 8; i++)
            #pragma unroll
            for (int j = 0; j < 4; j++) sacc[i][j] = 0.f;

        #pragma unroll
        for (int ks = 0; ks < 8; ks++) {
            int qb = (warp * 16 + gid) * FSQ + ks * 8 + tg;
            unsigned qa0 = Qs[qb];
            unsigned qa1 = Qs[qb + 8 * FSQ];
            unsigned qa2 = Qs[qb + 4];
            unsigned qa3 = Qs[qb + 8 * FSQ + 4];
            #pragma unroll
            for (int ni = 0; ni < 8; ni++) {
                int kb = (ni * 8 + gid) * FSQ + ks * 8 + tg;
                mma_tf32(sacc[ni], qa0, qa1, qa2, qa3, Ks[kb], Ks[kb + 4]);
            }
        }

        bool domask = (causal && (kvb + FBK - 1 > row0)) || (kvb + FBK > Tk);
        if (domask) {
            #pragma unroll
            for (int ni = 0; ni < 8; ni++) {
                #pragma unroll
                for (int s = 0; s < 4; s++) {
                    int col = kvb + ni * 8 + tg * 2 + (s & 1);
                    int r = (s < 2) ? r_0 : r_1;
                    bool ok = (col < Tk) && (!causal || col <= r);
                    if (!ok) sacc[ni][s] = -1e30f;
                }
            }
        }

        float tm0 = -1e30f, tm1 = -1e30f;
        #pragma unroll
        for (int ni = 0; ni < 8; ni++) {
            tm0 = fmaxf(tm0, fmaxf(sacc[ni][0], sacc[ni][1]));
            tm1 = fmaxf(tm1, fmaxf(sacc[ni][2], sacc[ni][3]));
        }
        tm0 = fmaxf(tm0, __shfl_xor_sync(0xffffffffu, tm0, 1));
        tm0 = fmaxf(tm0, __shfl_xor_sync(0xffffffffu, tm0, 2));
        tm1 = fmaxf(tm1, __shfl_xor_sync(0xffffffffu, tm1, 1));
        tm1 = fmaxf(tm1, __shfl_xor_sync(0xffffffffu, tm1, 2));

        float nm0 = fmaxf(m0, tm0), nm1 = fmaxf(m1, tm1);
        float sc0 = __expf(m0 - nm0), sc1 = __expf(m1 - nm1);
        m0 = nm0; m1 = nm1;

        float rs0 = 0.f, rs1 = 0.f;
        #pragma unroll
        for (int ni = 0; ni < 8; ni++) {
            sacc[ni][0] = __expf(sacc[ni][0] - nm0); rs0 += sacc[ni][0];
            sacc[ni][1] = __expf(sacc[ni][1] - nm0); rs0 += sacc[ni][1];
            sacc[ni][2] = __expf(sacc[ni][2] - nm1); rs1 += sacc[ni][2];
            sacc[ni][3] = __expf(sacc[ni][3] - nm1); rs1 += sacc[ni][3];
        }
        rs0 += __shfl_xor_sync(0xffffffffu, rs0, 1);
        rs0 += __shfl_xor_sync(0xffffffffu, rs0, 2);
        rs1 += __shfl_xor_sync(0xffffffffu, rs1, 1);
        rs1 += __shfl_xor_sync(0xffffffffu, rs1, 2);
        l0 = l0 * sc0 + rs0;
        l1 = l1 * sc1 + rs1;

        #pragma unroll
        for (int ni = 0; ni < 8; ni++) {
            o[ni][0] *= sc0; o[ni][1] *= sc0;
            o[ni][2] *= sc1; o[ni][3] *= sc1;
        }

        int bl = lane & ~3;
        int s0 = bl + (tg >> 1);
        int s1 = bl + 2 + (tg >> 1);
        bool hi = (tg & 1);
        #pragma unroll
        for (int ks = 0; ks < 8; ks++) {
            float p0 = sacc[ks][0], p1 = sacc[ks][1];
            float p2 = sacc[ks][2], p3 = sacc[ks][3];
            float v00 = __shfl_sync(0xffffffffu, p0, s0);
            float v01 = __shfl_sync(0xffffffffu, p1, s0);
            float v10 = __shfl_sync(0xffffffffu, p2, s0);
            float v11 = __shfl_sync(0xffffffffu, p3, s0);
            float w00 = __shfl_sync(0xffffffffu, p0, s1);
            float w01 = __shfl_sync(0xffffffffu, p1, s1);
            float w10 = __shfl_sync(0xffffffffu, p2, s1);
            float w11 = __shfl_sync(0xffffffffu, p3, s1);
            unsigned a0 = totf(hi ? v01 : v00);
            unsigned a1 = totf(hi ? v11 : v10);
            unsigned a2 = totf(hi ? w01 : w00);
            unsigned a3 = totf(hi ? w11 : w10);
            #pragma unroll
            for (int nj = 0; nj < 8; nj++) {
                int vb = (ks * 8 + tg) * FSV + nj * 8 + gid;
                mma_tf32(o[nj], a0, a1, a2, a3, Vs[vb], Vs[vb + 4 * FSV]);
            }
        }
    }

    // output rounded to tf32 (feeds next GEMM's A operand)
    float inv0 = 1.0f / l0, inv1 = 1.0f / l1;
    #pragma unroll
    for (int nj = 0; nj < 8; nj++) {
        int c = nj * 8 + tg * 2;
        if (r_0 < Tq) {
            float2 w = make_float2(totf_f(o[nj][0] * inv0), totf_f(o[nj][1] * inv0));
            *(float2*)(Op + (long)r_0 * ldo + c) = w;
        }
        if (r_1 < Tq) {
            float2 w = make_float2(totf_f(o[nj][2] * inv1), totf_f(o[nj][3] * inv1));
            *(float2*)(Op + (long)r_1 * ldo + c) = w;
        }
    }
}

// ================= cp.async 4-stage tf32 GEMM =================
// Requires: operands tf32-clean in gmem; K % 16 == 0; N % 128 == 0; ldc == N.
// EPI bits: 1=+bias, 2=+Res, 4=GELU, 8=round output to tf32
#define BM 128
#define BN 128
#define BK 16
#define NSTG 4
#define SAS 20                      // A smem row stride (words)
#define SBS 136                     // B smem row stride (words)
#define AW (BM * SAS)               // 2560 words per stage
#define BW (BK * SBS)               // 2176 words per stage
#define STG (AW + BW)               // 4736 words
#define GSMEM (STG * NSTG * 4)      // 75776 bytes

template<int EPI>
__global__ __launch_bounds__(256, 2) void tgemm(
    const float* __restrict__ A, const float* __restrict__ Bm,
    const float* __restrict__ bias, const float* __restrict__ Res,
    float* __restrict__ C,
    int M, int N, int K, int lda, int ldb)
{
    extern __shared__ unsigned dsm[];
    unsigned sbase = (unsigned)__cvta_generic_to_shared(dsm);

    int row0 = blockIdx.y * BM, col0 = blockIdx.x * BN;
    int tid  = threadIdx.x;
    int lane = tid & 31, warp = tid >> 5;
    int wm = (warp & 1) * 64;
    int wn = (warp >> 1) * 32;
    int gid = lane >> 2, tg = lane & 3;

    // load indices
    int ar = tid >> 1;                  // A: 2 chunks/thread over 128 rows
    int ak = (tid & 1) * 8;             // chunk pair: k offsets {0,8} then +4 chunk
    int bk = tid >> 5;                  // B: rows 0..7 (+8), 4-float chunks
    int bn = (tid & 31) * 4;

    auto load_stage = [&](int s, int k0) {
        unsigned abase = sbase + (s * STG) * 4;
        unsigned bbase = sbase + (s * STG + AW) * 4;
        // A: 128 rows x 16k  -> per thread: row=ar, k = ak and ak+4
        const float* asrc = A + (long)(row0 + ar) * lda + k0 + ak;
        bool av = (row0 + ar) < M;
        unsigned adst = abase + (ar * SAS + ak) * 4;
        cpa16(adst, asrc, av);
        cpa16(adst + 16, asrc + 4, av);
        // B: 16 rows x 128n -> per thread: k=bk,bk+8 n4=bn
        const float* bsrc = Bm + (long)(k0 + bk) * ldb + col0 + bn;
        unsigned bdst = bbase + (bk * SBS + bn) * 4;
        cpa16u(bdst, bsrc);
        cpa16u(bdst + SBS * 8 * 4, bsrc + (long)8 * ldb);
    };

    float acc[4][4][4];
    #pragma unroll
    for (int i = 0; i < 4; i++)
        #pragma unroll
        for (int j = 0; j < 4; j++)
            #pragma unroll
            for (int r = 0; r < 4; r++) acc[i][j][r] = 0.f;

    int ntiles = K / BK;

    #pragma unroll
    for (int s = 0; s < NSTG - 1; s++) {
        if (s < ntiles) load_stage(s, s * BK);
        cpa_commit();
    }

    for (int t = 0; t < ntiles; t++) {
        cpa_wait<NSTG - 2>();
        __syncthreads();

        int tn = t + NSTG - 1;
        if (tn < ntiles) load_stage(tn % NSTG, tn * BK);
        cpa_commit();

        int buf = t % NSTG;
        const unsigned* As = dsm + buf * STG;
        const unsigned* Bs = dsm + buf * STG + AW;

        #pragma unroll
        for (int ks = 0; ks < 2; ks++) {
            int k0s = ks * 8;
            unsigned a[4][4], b[4][2];
            #pragma unroll
            for (int mi = 0; mi < 4; mi++) {
                int r = wm + mi * 16 + gid;
                a[mi][0] = As[r * SAS + k0s + tg];
                a[mi][1] = As[(r + 8) * SAS + k0s + tg];
                a[mi][2] = As[r * SAS + k0s + tg + 4];
                a[mi][3] = As[(r + 8) * SAS + k0s + tg + 4];
            }
            #pragma unroll
            for (int ni = 0; ni < 4; ni++) {
                int n = wn + ni * 8 + gid;
                b[ni][0] = Bs[(k0s + tg) * SBS + n];
                b[ni][1] = Bs[(k0s + tg + 4) * SBS + n];
            }
            #pragma unroll
            for (int mi = 0; mi < 4; mi++)
                #pragma unroll
                for (int ni = 0; ni < 4; ni++)
                    mma_tf32(acc[mi][ni], a[mi][0], a[mi][1], a[mi][2], a[mi][3],
                             b[ni][0], b[ni][1]);
        }
    }

    #pragma unroll
    for (int mi = 0; mi < 4; mi++) {
        #pragma unroll
        for (int ni = 0; ni < 4; ni++) {
            #pragma unroll
            for (int rr = 0; rr < 2; rr++) {
                int r = row0 + wm + mi * 16 + gid + rr * 8;
                if (r >= M) continue;
                #pragma unroll
                for (int cc = 0; cc < 2; cc++) {
                    int c = col0 + wn + ni * 8 + tg * 2 + cc;
                    float v = acc[mi][ni][rr * 2 + cc];
                    if (EPI & 1) v += bias[c];
                    if (EPI & 4) v = 0.5f * v * (1.0f + erff(v * 0.70710678118654752f));
                    if (EPI & 2) v += Res[(long)r * N + c];
                    if (EPI & 8) v = totf_f(v);
                    C[(long)r * N + c] = v;
                }
            }
        }
    }
}

// ---------------- host side ----------------
static inline dim3 ggrid(int M, int N) {
    return dim3((unsigned)((N + BN - 1) / BN), (unsigned)((M + BM - 1) / BM), 1);
}

extern "C" void kernel_launch(void* const* d_in, const int* in_sizes, int n_in,
                              void* d_out, int out_size)
{
    const float* x        = (const float*)d_in[0];
    const float* cond     = (const float*)d_in[1];
    const float* Wqkv     = (const float*)d_in[2];
    const float* Wproj_sa = (const float*)d_in[3];
    const float* bproj_sa = (const float*)d_in[4];
    const float* g1       = (const float*)d_in[5];
    const float* b1       = (const float*)d_in[6];
    const float* Wq_ca    = (const float*)d_in[7];
    const float* Wkv_ca   = (const float*)d_in[8];
    const float* Wproj_ca = (const float*)d_in[9];
    const float* bproj_ca = (const float*)d_in[10];
    const float* g2       = (const float*)d_in[11];
    const float* b2       = (const float*)d_in[12];
    const float* Wff1     = (const float*)d_in[13];
    const float* bff1     = (const float*)d_in[14];
    const float* Wff2     = (const float*)d_in[15];
    const float* bff2     = (const float*)d_in[16];
    const float* g3       = (const float*)d_in[17];
    const float* b3       = (const float*)d_in[18];
    float* out            = (float*)d_out;

    float *p_ln, *p_qkv, *p_attn, *p_x1, *p_x2, *p_qca, *p_kvca, *p_ff, *p_w;
    cudaGetSymbolAddress((void**)&p_ln,   g_ln);
    cudaGetSymbolAddress((void**)&p_qkv,  g_qkv);
    cudaGetSymbolAddress((void**)&p_attn, g_attn);
    cudaGetSymbolAddress((void**)&p_x1,   g_x1);
    cudaGetSymbolAddress((void**)&p_x2,   g_x2);
    cudaGetSymbolAddress((void**)&p_qca,  g_qca);
    cudaGetSymbolAddress((void**)&p_kvca, g_kvca);
    cudaGetSymbolAddress((void**)&p_ff,   g_ff);
    cudaGetSymbolAddress((void**)&p_w,    g_w);

    static int smem_set = 0;
    if (!smem_set) {
        cudaFuncSetAttribute(flash_kernel, cudaFuncAttributeMaxDynamicSharedMemorySize, FSMEM);
        cudaFuncSetAttribute(tgemm<8>,  cudaFuncAttributeMaxDynamicSharedMemorySize, GSMEM);
        cudaFuncSetAttribute(tgemm<3>,  cudaFuncAttributeMaxDynamicSharedMemorySize, GSMEM);
        cudaFuncSetAttribute(tgemm<13>, cudaFuncAttributeMaxDynamicSharedMemorySize, GSMEM);
        smem_set = 1;
    }

    const long T3D = (long)Tt * 3 * Dm;
    const long TD  = (long)Tt * Dm;
    const long KVb = (long)Cc * 2 * Dm;
    const float iscale = 0.125f;

    // 0) tf32-round all weights + cond into scratch
    round_kernel<<<4096, 256>>>(Wqkv,     p_w + OW_QKV,  Dm*3*Dm);
    round_kernel<<<2048, 256>>>(Wproj_sa, p_w + OW_PSA,  Dm*Dm);
    round_kernel<<<2048, 256>>>(Wq_ca,    p_w + OW_QCA,  Dm*Dm);
    round_kernel<<<2048, 256>>>(Wkv_ca,   p_w + OW_KVCA, DC*2*Dm);
    round_kernel<<<2048, 256>>>(Wproj_ca, p_w + OW_PCA,  Dm*Dm);
    round_kernel<<<4096, 256>>>(Wff1,     p_w + OW_FF1,  Dm*DFF);
    round_kernel<<<4096, 256>>>(Wff2,     p_w + OW_FF2,  DFF*Dm);
    round_kernel<<<232,  256>>>(cond,     p_w + OW_COND, Bb*Cc*DC);

    // 1) ln1 = LN(x)
    ln_kernel<<<MX, 256>>>(x, g1, b1, p_ln);

    // 2) qkv = ln1 @ Wqkv   (rounded output -> flash inputs)
    tgemm<8><<<ggrid(MX, 3*Dm), 256, GSMEM>>>(
        p_ln, p_w + OW_QKV, nullptr, nullptr, p_qkv, MX, 3*Dm, Dm, Dm, 3*Dm);

    // 3) fused causal self-attention -> g_attn
    flash_kernel<<<dim3(1, Tt/FBQ, Bb*Hh), 256, FSMEM>>>(
        p_qkv, p_qkv + Dm, p_qkv + 2*Dm, p_attn,
        Tt, Tt, 3*Dm, 3*Dm, Dm,
        T3D, DH, T3D, DH, TD, DH, Hh, iscale, 1);

    // 4) x1 = x + attn @ Wproj_sa + b
    tgemm<3><<<ggrid(MX, Dm), 256, GSMEM>>>(
        p_attn, p_w + OW_PSA, bproj_sa, x, p_x1, MX, Dm, Dm, Dm, Dm);

    // 5) ln2 = LN(x1)
    ln_kernel<<<MX, 256>>>(p_x1, g2, b2, p_ln);

    // 6) q_ca = ln2 @ Wq_ca  (rounded -> flash)
    tgemm<8><<<ggrid(MX, Dm), 256, GSMEM>>>(
        p_ln, p_w + OW_QCA, nullptr, nullptr, p_qca, MX, Dm, Dm, Dm, Dm);

    // 7) kv_ca = cond_r @ Wkv_ca (rounded -> flash)
    tgemm<8><<<ggrid(Bb*Cc, 2*Dm), 256, GSMEM>>>(
        p_w + OW_COND, p_w + OW_KVCA, nullptr, nullptr, p_kvca,
        Bb*Cc, 2*Dm, DC, DC, 2*Dm);

    // 8) fused cross-attention -> g_attn
    flash_kernel<<<dim3(1, Tt/FBQ, Bb*Hh), 256, FSMEM>>>(
        p_qca, p_kvca, p_kvca + Dm, p_attn,
        Tt, Cc, Dm, 2*Dm, Dm,
        TD, DH, KVb, DH, TD, DH, Hh, iscale, 0);

    // 9) x2 = x1 + ca_out @ Wproj_ca + b
    tgemm<3><<<ggrid(MX, Dm), 256, GSMEM>>>(
        p_attn, p_w + OW_PCA, bproj_ca, p_x1, p_x2, MX, Dm, Dm, Dm, Dm);

    // 10) ln3 = LN(x2)
    ln_kernel<<<MX, 256>>>(p_x2, g3, b3, p_ln);

    // 11) ffh = gelu(ln3 @ Wff1 + bff1), rounded
    tgemm<13><<<ggrid(MX, DFF), 256, GSMEM>>>(
        p_ln, p_w + OW_FF1, bff1, nullptr, p_ff, MX, DFF, Dm, Dm, DFF);

    // 12) out = x2 + ffh @ Wff2 + bff2
    tgemm<3><<<ggrid(MX, Dm), 256, GSMEM>>>(
        p_ff, p_w + OW_FF2, bff2, p_x2, out, MX, Dm, DFF, DFF, Dm);
}

// round 6
// speedup vs baseline: 5.5137x; 1.0532x over previous
#include <cuda_runtime.h>
#include <math.h>

// ---------------- problem constants ----------------
#define Dm   1024
#define Hh   16
#define DH   64
#define DFF  4096
#define DC   768
#define Tt   2048
#define Bb   2
#define Cc   77
#define MX   4096          // Bb*Tt rows of x

// ---------------- scratch (static device arrays; no allocs) ----------------
__device__ float g_ln   [(size_t)MX * Dm];
__device__ float g_qkv  [(size_t)MX * 3 * Dm];
__device__ float g_attn [(size_t)MX * Dm];
__device__ float g_x1   [(size_t)MX * Dm];
__device__ float g_x2   [(size_t)MX * Dm];
__device__ float g_qca  [(size_t)MX * Dm];
__device__ float g_kvca [(size_t)Bb * Cc * 2 * Dm];
__device__ float g_ff   [(size_t)MX * DFF];
__device__ float g_w    [(size_t)16400000];          // tf32-rounded weights + cond

// weight-scratch offsets (floats) - contiguous, in rounding order
#define SZ_QKV  (Dm*3*Dm)
#define SZ_PSA  (Dm*Dm)
#define SZ_QCA  (Dm*Dm)
#define SZ_KVCA (DC*2*Dm)
#define SZ_PCA  (Dm*Dm)
#define SZ_FF1  (Dm*DFF)
#define SZ_FF2  (DFF*Dm)
#define SZ_COND (Bb*Cc*DC)
#define OW_QKV   0
#define OW_PSA   (OW_QKV + SZ_QKV)
#define OW_QCA   (OW_PSA + SZ_PSA)
#define OW_KVCA  (OW_QCA + SZ_QCA)
#define OW_PCA   (OW_KVCA + SZ_KVCA)
#define OW_FF1   (OW_PCA + SZ_PCA)
#define OW_FF2   (OW_FF1 + SZ_FF1)
#define OW_COND  (OW_FF2 + SZ_FF2)
#define OW_TOT   (OW_COND + SZ_COND)

// ---------------- tf32 helpers ----------------
__device__ __forceinline__ unsigned totf(float f) {
    unsigned u;
    asm("cvt.rna.tf32.f32 %0, %1;" : "=r"(u) : "f"(f));
    return u;
}
__device__ __forceinline__ float totf_f(float f) { return __uint_as_float(totf(f)); }

__device__ __forceinline__ void mma_tf32(float c[4],
    unsigned a0, unsigned a1, unsigned a2, unsigned a3,
    unsigned b0, unsigned b1)
{
    asm volatile(
        "mma.sync.aligned.m16n8k8.row.col.f32.tf32.tf32.f32 "
        "{%0,%1,%2,%3}, {%4,%5,%6,%7}, {%8,%9}, {%0,%1,%2,%3};\n"
        : "+f"(c[0]), "+f"(c[1]), "+f"(c[2]), "+f"(c[3])
        : "r"(a0), "r"(a1), "r"(a2), "r"(a3), "r"(b0), "r"(b1));
}

__device__ __forceinline__ void cpa16(unsigned dst, const float* src, bool pred) {
    int sz = pred ? 16 : 0;
    asm volatile("cp.async.cg.shared.global [%0], [%1], 16, %2;\n"
                 :: "r"(dst), "l"(src), "r"(sz));
}
__device__ __forceinline__ void cpa16u(unsigned dst, const float* src) {
    asm volatile("cp.async.cg.shared.global [%0], [%1], 16;\n"
                 :: "r"(dst), "l"(src));
}
__device__ __forceinline__ void cpa_commit() {
    asm volatile("cp.async.commit_group;\n");
}
template<int N>
__device__ __forceinline__ void cpa_wait() {
    asm volatile("cp.async.wait_group %0;\n" :: "n"(N));
}

// ---------------- merged weight rounding prep (one launch) ----------------
__global__ __launch_bounds__(256) void round_all_kernel(
    const float* __restrict__ s0, const float* __restrict__ s1,
    const float* __restrict__ s2, const float* __restrict__ s3,
    const float* __restrict__ s4, const float* __restrict__ s5,
    const float* __restrict__ s6, const float* __restrict__ s7,
    float* __restrict__ dst)
{
    int n4 = OW_TOT / 4;
    for (int i = blockIdx.x * 256 + threadIdx.x; i < n4; i += gridDim.x * 256) {
        int idx = i * 4;
        const float* src;
        if      (idx < OW_PSA)  src = s0 + (idx - OW_QKV);
        else if (idx < OW_QCA)  src = s1 + (idx - OW_PSA);
        else if (idx < OW_KVCA) src = s2 + (idx - OW_QCA);
        else if (idx < OW_PCA)  src = s3 + (idx - OW_KVCA);
        else if (idx < OW_FF1)  src = s4 + (idx - OW_PCA);
        else if (idx < OW_FF2)  src = s5 + (idx - OW_FF1);
        else if (idx < OW_COND) src = s6 + (idx - OW_FF2);
        else                    src = s7 + (idx - OW_COND);
        float4 v = *(const float4*)src;
        v.x = totf_f(v.x); v.y = totf_f(v.y);
        v.z = totf_f(v.z); v.w = totf_f(v.w);
        *(float4*)(dst + idx) = v;
    }
}

// ---------------- reductions ----------------
__device__ __forceinline__ float block_sum(float v, float* sh) {
    #pragma unroll
    for (int o = 16; o > 0; o >>= 1) v += __shfl_xor_sync(0xffffffffu, v, o);
    int w = threadIdx.x >> 5;
    if ((threadIdx.x & 31) == 0) sh[w] = v;
    __syncthreads();
    if (threadIdx.x < 32) {
        float t = (threadIdx.x < 8) ? sh[threadIdx.x] : 0.f;
        #pragma unroll
        for (int o = 4; o > 0; o >>= 1) t += __shfl_xor_sync(0xffffffffu, t, o);
        if (threadIdx.x == 0) sh[0] = t;
    }
    __syncthreads();
    float r = sh[0];
    __syncthreads();
    return r;
}

// ---------------- LayerNorm (tf32-rounded output) ----------------
__global__ __launch_bounds__(256) void ln_kernel(
    const float* __restrict__ x, const float* __restrict__ g,
    const float* __restrict__ b, float* __restrict__ out)
{
    __shared__ float sh[8];
    long row = blockIdx.x;
    const float4* xr = (const float4*)(x + row * Dm);
    int tid = threadIdx.x;
    float4 v = xr[tid];
    float s = v.x + v.y + v.z + v.w;
    s = block_sum(s, sh);
    float mean = s * (1.0f / Dm);
    float dx = v.x - mean, dy = v.y - mean, dz = v.z - mean, dw = v.w - mean;
    float s2 = dx*dx + dy*dy + dz*dz + dw*dw;
    s2 = block_sum(s2, sh);
    float rstd = rsqrtf(s2 * (1.0f / Dm) + 1e-5f);
    float4 gg = ((const float4*)g)[tid];
    float4 bbv = ((const float4*)b)[tid];
    float4 o;
    o.x = totf_f(dx * rstd * gg.x + bbv.x);
    o.y = totf_f(dy * rstd * gg.y + bbv.y);
    o.z = totf_f(dz * rstd * gg.z + bbv.z);
    o.w = totf_f(dw * rstd * gg.w + bbv.w);
    ((float4*)(out + row * Dm))[tid] = o;
}

// ================= fused flash attention (tf32, pre-rounded inputs) =================
#define FBQ 128
#define FBK 64
#define FSQ 68
#define FSV 72
#define FSMEM ((FBQ*FSQ + FBK*FSQ + FBK*FSV) * 4)

__global__ __launch_bounds__(256, 2) void flash_kernel(
    const float* __restrict__ Qp, const float* __restrict__ Kp,
    const float* __restrict__ Vp, float* __restrict__ Op,
    int Tq, int Tk, int ldq, int ldk, int ldo,
    long sQb, long sQh, long sKb, long sKh, long sOb, long sOh,
    int Hn, float scale, int causal)
{
    extern __shared__ unsigned fsm[];
    unsigned* Qs = fsm;
    unsigned* Ks = fsm + FBQ * FSQ;
    unsigned* Vs = Ks + FBK * FSQ;

    int z = blockIdx.z, zb = z / Hn, zh = z - zb * Hn;
    Qp += zb * sQb + zh * sQh;
    Kp += zb * sKb + zh * sKh;
    Vp += zb * sKb + zh * sKh;
    Op += zb * sOb + zh * sOh;

    int tid = threadIdx.x, lane = tid & 31, warp = tid >> 5;
    int gid = lane >> 2, tg = lane & 3;
    int row0 = blockIdx.y * FBQ;

    #pragma unroll
    for (int it = 0; it < 8; it++) {
        int idx = it * 256 + tid;
        int r = idx >> 4, c4 = (idx & 15) * 4;
        int gr = row0 + r;
        float4 v = make_float4(0.f, 0.f, 0.f, 0.f);
        if (gr < Tq) v = *(const float4*)(Qp + (long)gr * ldq + c4);
        unsigned* q = &Qs[r * FSQ + c4];
        q[0] = __float_as_uint(v.x * scale); q[1] = __float_as_uint(v.y * scale);
        q[2] = __float_as_uint(v.z * scale); q[3] = __float_as_uint(v.w * scale);
    }

    int r_0 = row0 + warp * 16 + gid;
    int r_1 = r_0 + 8;

    float m0 = -1e30f, m1 = -1e30f, l0 = 0.f, l1 = 0.f;
    float o[8][4];
    #pragma unroll
    for (int i = 0; i < 8; i++)
        #pragma unroll
        for (int j = 0; j < 4; j++) o[i][j] = 0.f;

    int ntile = causal ? (row0 + FBQ) / FBK : (Tk + FBK - 1) / FBK;

    for (int t = 0; t < ntile; t++) {
        int kvb = t * FBK;
        __syncthreads();
        #pragma unroll
        for (int it = 0; it < 4; it++) {
            int idx = it * 256 + tid;
            int r = idx >> 4, c4 = (idx & 15) * 4;
            int gr = kvb + r;
            float4 kv = make_float4(0.f,0.f,0.f,0.f), vv = make_float4(0.f,0.f,0.f,0.f);
            if (gr < Tk) {
                kv = *(const float4*)(Kp + (long)gr * ldk + c4);
                vv = *(const float4*)(Vp + (long)gr * ldk + c4);
            }
            unsigned* k = &Ks[r * FSQ + c4];
            k[0] = __float_as_uint(kv.x); k[1] = __float_as_uint(kv.y);
            k[2] = __float_as_uint(kv.z); k[3] = __float_as_uint(kv.w);
            unsigned* v = &Vs[r * FSV + c4];
            v[0] = __float_as_uint(vv.x); v[1] = __float_as_uint(vv.y);
            v[2] = __float_as_uint(vv.z); v[3] = __float_as_uint(vv.w);
        }
        __syncthreads();

        float sacc[8][4];
        #pragma unroll
        for (int i = 0; i < 8; i++)
            #pragma unroll
            for (int j = 0; j < 4; j++) sacc[i][j] = 0.f;

        #pragma unroll
        for (int ks = 0; ks < 8; ks++) {
            int qb = (warp * 16 + gid) * FSQ + ks * 8 + tg;
            unsigned qa0 = Qs[qb];
            unsigned qa1 = Qs[qb + 8 * FSQ];
            unsigned qa2 = Qs[qb + 4];
            unsigned qa3 = Qs[qb + 8 * FSQ + 4];
            #pragma unroll
            for (int ni = 0; ni < 8; ni++) {
                int kb = (ni * 8 + gid) * FSQ + ks * 8 + tg;
                mma_tf32(sacc[ni], qa0, qa1, qa2, qa3, Ks[kb], Ks[kb + 4]);
            }
        }

        bool domask = (causal && (kvb + FBK - 1 > row0)) || (kvb + FBK > Tk);
        if (domask) {
            #pragma unroll
            for (int ni = 0; ni < 8; ni++) {
                #pragma unroll
                for (int s = 0; s < 4; s++) {
                    int col = kvb + ni * 8 + tg * 2 + (s & 1);
                    int r = (s < 2) ? r_0 : r_1;
                    bool ok = (col < Tk) && (!causal || col <= r);
                    if (!ok) sacc[ni][s] = -1e30f;
                }
            }
        }

        float tm0 = -1e30f, tm1 = -1e30f;
        #pragma unroll
        for (int ni = 0; ni < 8; ni++) {
            tm0 = fmaxf(tm0, fmaxf(sacc[ni][0], sacc[ni][1]));
            tm1 = fmaxf(tm1, fmaxf(sacc[ni][2], sacc[ni][3]));
        }
        tm0 = fmaxf(tm0, __shfl_xor_sync(0xffffffffu, tm0, 1));
        tm0 = fmaxf(tm0, __shfl_xor_sync(0xffffffffu, tm0, 2));
        tm1 = fmaxf(tm1, __shfl_xor_sync(0xffffffffu, tm1, 1));
        tm1 = fmaxf(tm1, __shfl_xor_sync(0xffffffffu, tm1, 2));

        float nm0 = fmaxf(m0, tm0), nm1 = fmaxf(m1, tm1);
        float sc0 = __expf(m0 - nm0), sc1 = __expf(m1 - nm1);
        m0 = nm0; m1 = nm1;

        float rs0 = 0.f, rs1 = 0.f;
        #pragma unroll
        for (int ni = 0; ni < 8; ni++) {
            sacc[ni][0] = __expf(sacc[ni][0] - nm0); rs0 += sacc[ni][0];
            sacc[ni][1] = __expf(sacc[ni][1] - nm0); rs0 += sacc[ni][1];
            sacc[ni][2] = __expf(sacc[ni][2] - nm1); rs1 += sacc[ni][2];
            sacc[ni][3] = __expf(sacc[ni][3] - nm1); rs1 += sacc[ni][3];
        }
        rs0 += __shfl_xor_sync(0xffffffffu, rs0, 1);
        rs0 += __shfl_xor_sync(0xffffffffu, rs0, 2);
        rs1 += __shfl_xor_sync(0xffffffffu, rs1, 1);
        rs1 += __shfl_xor_sync(0xffffffffu, rs1, 2);
        l0 = l0 * sc0 + rs0;
        l1 = l1 * sc1 + rs1;

        #pragma unroll
        for (int ni = 0; ni < 8; ni++) {
            o[ni][0] *= sc0; o[ni][1] *= sc0;
            o[ni][2] *= sc1; o[ni][3] *= sc1;
        }

        int bl = lane & ~3;
        int s0 = bl + (tg >> 1);
        int s1 = bl + 2 + (tg >> 1);
        bool hi = (tg & 1);
        #pragma unroll
        for (int ks = 0; ks < 8; ks++) {
            float p0 = sacc[ks][0], p1 = sacc[ks][1];
            float p2 = sacc[ks][2], p3 = sacc[ks][3];
            float v00 = __shfl_sync(0xffffffffu, p0, s0);
            float v01 = __shfl_sync(0xffffffffu, p1, s0);
            float v10 = __shfl_sync(0xffffffffu, p2, s0);
            float v11 = __shfl_sync(0xffffffffu, p3, s0);
            float w00 = __shfl_sync(0xffffffffu, p0, s1);
            float w01 = __shfl_sync(0xffffffffu, p1, s1);
            float w10 = __shfl_sync(0xffffffffu, p2, s1);
            float w11 = __shfl_sync(0xffffffffu, p3, s1);
            unsigned a0 = totf(hi ? v01 : v00);
            unsigned a1 = totf(hi ? v11 : v10);
            unsigned a2 = totf(hi ? w01 : w00);
            unsigned a3 = totf(hi ? w11 : w10);
            #pragma unroll
            for (int nj = 0; nj < 8; nj++) {
                int vb = (ks * 8 + tg) * FSV + nj * 8 + gid;
                mma_tf32(o[nj], a0, a1, a2, a3, Vs[vb], Vs[vb + 4 * FSV]);
            }
        }
    }

    float inv0 = 1.0f / l0, inv1 = 1.0f / l1;
    #pragma unroll
    for (int nj = 0; nj < 8; nj++) {
        int c = nj * 8 + tg * 2;
        if (r_0 < Tq) {
            float2 w = make_float2(totf_f(o[nj][0] * inv0), totf_f(o[nj][1] * inv0));
            *(float2*)(Op + (long)r_0 * ldo + c) = w;
        }
        if (r_1 < Tq) {
            float2 w = make_float2(totf_f(o[nj][2] * inv1), totf_f(o[nj][3] * inv1));
            *(float2*)(Op + (long)r_1 * ldo + c) = w;
        }
    }
}

// ================= cp.async 4-stage tf32 GEMM, 128x256 block, 64x64 warp tile ========
// Requires: operands tf32-clean in gmem; K % 16 == 0; N % 256 == 0; ldc == N.
// EPI bits: 1=+bias, 2=+Res, 4=GELU, 8=round output to tf32
#define BM 128
#define BN 256
#define BK 16
#define NSTG 4
#define SAS 20                      // A smem row stride (words)
#define SBS 264                     // B smem row stride (words) for 256-wide rows
#define AW (BM * SAS)               // 2560 words per stage
#define BW (BK * SBS)               // 4224 words per stage
#define STG (AW + BW)               // 6784 words
#define GSMEM (STG * NSTG * 4)      // 108544 bytes

template<int EPI>
__global__ __launch_bounds__(256, 1) void tgemm(
    const float* __restrict__ A, const float* __restrict__ Bm,
    const float* __restrict__ bias, const float* __restrict__ Res,
    float* __restrict__ C,
    int M, int N, int K, int lda, int ldb)
{
    extern __shared__ unsigned dsm[];
    unsigned sbase = (unsigned)__cvta_generic_to_shared(dsm);

    int row0 = blockIdx.y * BM, col0 = blockIdx.x * BN;
    int tid  = threadIdx.x;
    int lane = tid & 31, warp = tid >> 5;
    int wm = (warp & 1) * 64;             // 2 warps over M
    int wn = (warp >> 1) * 64;            // 4 warps over N
    int gid = lane >> 2, tg = lane & 3;

    // load indices
    int ar = tid >> 1;                    // A: rows 0..127, 2 chunks each
    int ak = (tid & 1) * 8;
    int bk = tid >> 6;                    // B: base row 0..3 (+4 step), 4 chunks
    int bn = (tid & 63) * 4;

    auto load_stage = [&](int s, int k0) {
        unsigned abase = sbase + (s * STG) * 4;
        unsigned bbase = sbase + (s * STG + AW) * 4;
        const float* asrc = A + (long)(row0 + ar) * lda + k0 + ak;
        bool av = (row0 + ar) < M;
        unsigned adst = abase + (ar * SAS + ak) * 4;
        cpa16(adst, asrc, av);
        cpa16(adst + 16, asrc + 4, av);
        const float* bsrc = Bm + (long)(k0 + bk) * ldb + col0 + bn;
        unsigned bdst = bbase + (bk * SBS + bn) * 4;
        #pragma unroll
        for (int i = 0; i < 4; i++)
            cpa16u(bdst + i * (SBS * 4 * 4), bsrc + (long)(4 * i) * ldb);
    };

    float acc[4][8][4];
    #pragma unroll
    for (int i = 0; i < 4; i++)
        #pragma unroll
        for (int j = 0; j < 8; j++)
            #pragma unroll
            for (int r = 0; r < 4; r++) acc[i][j][r] = 0.f;

    int ntiles = K / BK;

    #pragma unroll
    for (int s = 0; s < NSTG - 1; s++) {
        if (s < ntiles) load_stage(s, s * BK);
        cpa_commit();
    }

    for (int t = 0; t < ntiles; t++) {
        cpa_wait<NSTG - 2>();
        __syncthreads();

        int tn = t + NSTG - 1;
        if (tn < ntiles) load_stage(tn % NSTG, tn * BK);
        cpa_commit();

        int buf = t % NSTG;
        const unsigned* As = dsm + buf * STG;
        const unsigned* Bs = dsm + buf * STG + AW;

        #pragma unroll
        for (int ks = 0; ks < 2; ks++) {
            int k0s = ks * 8;
            unsigned a[4][4], b[8][2];
            #pragma unroll
            for (int mi = 0; mi < 4; mi++) {
                int r = wm + mi * 16 + gid;
                a[mi][0] = As[r * SAS + k0s + tg];
                a[mi][1] = As[(r + 8) * SAS + k0s + tg];
                a[mi][2] = As[r * SAS + k0s + tg + 4];
                a[mi][3] = As[(r + 8) * SAS + k0s + tg + 4];
            }
            #pragma unroll
            for (int ni = 0; ni < 8; ni++) {
                int n = wn + ni * 8 + gid;
                b[ni][0] = Bs[(k0s + tg) * SBS + n];
                b[ni][1] = Bs[(k0s + tg + 4) * SBS + n];
            }
            #pragma unroll
            for (int mi = 0; mi < 4; mi++)
                #pragma unroll
                for (int ni = 0; ni < 8; ni++)
                    mma_tf32(acc[mi][ni], a[mi][0], a[mi][1], a[mi][2], a[mi][3],
                             b[ni][0], b[ni][1]);
        }
    }

    #pragma unroll
    for (int mi = 0; mi < 4; mi++) {
        #pragma unroll
        for (int rr = 0; rr < 2; rr++) {
            int r = row0 + wm + mi * 16 + gid + rr * 8;
            if (r >= M) continue;
            #pragma unroll
            for (int ni = 0; ni < 8; ni++) {
                int c = col0 + wn + ni * 8 + tg * 2;
                float v0 = acc[mi][ni][rr * 2 + 0];
                float v1 = acc[mi][ni][rr * 2 + 1];
                if (EPI & 1) { v0 += bias[c]; v1 += bias[c + 1]; }
                if (EPI & 4) {
                    v0 = 0.5f * v0 * (1.0f + erff(v0 * 0.70710678118654752f));
                    v1 = 0.5f * v1 * (1.0f + erff(v1 * 0.70710678118654752f));
                }
                if (EPI & 2) {
                    float2 rv = *(const float2*)(Res + (long)r * N + c);
                    v0 += rv.x; v1 += rv.y;
                }
                if (EPI & 8) { v0 = totf_f(v0); v1 = totf_f(v1); }
                *(float2*)(C + (long)r * N + c) = make_float2(v0, v1);
            }
        }
    }
}

// ---------------- host side ----------------
static inline dim3 ggrid(int M, int N) {
    return dim3((unsigned)((N + BN - 1) / BN), (unsigned)((M + BM - 1) / BM), 1);
}

extern "C" void kernel_launch(void* const* d_in, const int* in_sizes, int n_in,
                              void* d_out, int out_size)
{
    const float* x        = (const float*)d_in[0];
    const float* cond     = (const float*)d_in[1];
    const float* Wqkv     = (const float*)d_in[2];
    const float* Wproj_sa = (const float*)d_in[3];
    const float* bproj_sa = (const float*)d_in[4];
    const float* g1       = (const float*)d_in[5];
    const float* b1       = (const float*)d_in[6];
    const float* Wq_ca    = (const float*)d_in[7];
    const float* Wkv_ca   = (const float*)d_in[8];
    const float* Wproj_ca = (const float*)d_in[9];
    const float* bproj_ca = (const float*)d_in[10];
    const float* g2       = (const float*)d_in[11];
    const float* b2       = (const float*)d_in[12];
    const float* Wff1     = (const float*)d_in[13];
    const float* bff1     = (const float*)d_in[14];
    const float* Wff2     = (const float*)d_in[15];
    const float* bff2     = (const float*)d_in[16];
    const float* g3       = (const float*)d_in[17];
    const float* b3       = (const float*)d_in[18];
    float* out            = (float*)d_out;

    float *p_ln, *p_qkv, *p_attn, *p_x1, *p_x2, *p_qca, *p_kvca, *p_ff, *p_w;
    cudaGetSymbolAddress((void**)&p_ln,   g_ln);
    cudaGetSymbolAddress((void**)&p_qkv,  g_qkv);
    cudaGetSymbolAddress((void**)&p_attn, g_attn);
    cudaGetSymbolAddress((void**)&p_x1,   g_x1);
    cudaGetSymbolAddress((void**)&p_x2,   g_x2);
    cudaGetSymbolAddress((void**)&p_qca,  g_qca);
    cudaGetSymbolAddress((void**)&p_kvca, g_kvca);
    cudaGetSymbolAddress((void**)&p_ff,   g_ff);
    cudaGetSymbolAddress((void**)&p_w,    g_w);

    static int smem_set = 0;
    if (!smem_set) {
        cudaFuncSetAttribute(flash_kernel, cudaFuncAttributeMaxDynamicSharedMemorySize, FSMEM);
        cudaFuncSetAttribute(tgemm<8>,  cudaFuncAttributeMaxDynamicSharedMemorySize, GSMEM);
        cudaFuncSetAttribute(tgemm<3>,  cudaFuncAttributeMaxDynamicSharedMemorySize, GSMEM);
        cudaFuncSetAttribute(tgemm<13>, cudaFuncAttributeMaxDynamicSharedMemorySize, GSMEM);
        smem_set = 1;
    }

    const long T3D = (long)Tt * 3 * Dm;
    const long TD  = (long)Tt * Dm;
    const long KVb = (long)Cc * 2 * Dm;
    const float iscale = 0.125f;

    // 0) tf32-round all weights + cond into scratch (single launch)
    round_all_kernel<<<2048, 256>>>(Wqkv, Wproj_sa, Wq_ca, Wkv_ca,
                                    Wproj_ca, Wff1, Wff2, cond, p_w);

    // 1) ln1 = LN(x)
    ln_kernel<<<MX, 256>>>(x, g1, b1, p_ln);

    // 2) qkv = ln1 @ Wqkv   (rounded output -> flash inputs)
    tgemm<8><<<ggrid(MX, 3*Dm), 256, GSMEM>>>(
        p_ln, p_w + OW_QKV, nullptr, nullptr, p_qkv, MX, 3*Dm, Dm, Dm, 3*Dm);

    // 3) fused causal self-attention -> g_attn
    flash_kernel<<<dim3(1, Tt/FBQ, Bb*Hh), 256, FSMEM>>>(
        p_qkv, p_qkv + Dm, p_qkv + 2*Dm, p_attn,
        Tt, Tt, 3*Dm, 3*Dm, Dm,
        T3D, DH, T3D, DH, TD, DH, Hh, iscale, 1);

    // 4) x1 = x + attn @ Wproj_sa + b
    tgemm<3><<<ggrid(MX, Dm), 256, GSMEM>>>(
        p_attn, p_w + OW_PSA, bproj_sa, x, p_x1, MX, Dm, Dm, Dm, Dm);

    // 5) ln2 = LN(x1)
    ln_kernel<<<MX, 256>>>(p_x1, g2, b2, p_ln);

    // 6) q_ca = ln2 @ Wq_ca  (rounded -> flash)
    tgemm<8><<<ggrid(MX, Dm), 256, GSMEM>>>(
        p_ln, p_w + OW_QCA, nullptr, nullptr, p_qca, MX, Dm, Dm, Dm, Dm);

    // 7) kv_ca = cond_r @ Wkv_ca (rounded -> flash)
    tgemm<8><<<ggrid(Bb*Cc, 2*Dm), 256, GSMEM>>>(
        p_w + OW_COND, p_w + OW_KVCA, nullptr, nullptr, p_kvca,
        Bb*Cc, 2*Dm, DC, DC, 2*Dm);

    // 8) fused cross-attention -> g_attn
    flash_kernel<<<dim3(1, Tt/FBQ, Bb*Hh), 256, FSMEM>>>(
        p_qca, p_kvca, p_kvca + Dm, p_attn,
        Tt, Cc, Dm, 2*Dm, Dm,
        TD, DH, KVb, DH, TD, DH, Hh, iscale, 0);

    // 9) x2 = x1 + ca_out @ Wproj_ca + b
    tgemm<3><<<ggrid(MX, Dm), 256, GSMEM>>>(
        p_attn, p_w + OW_PCA, bproj_ca, p_x1, p_x2, MX, Dm, Dm, Dm, Dm);

    // 10) ln3 = LN(x2)
    ln_kernel<<<MX, 256>>>(p_x2, g3, b3, p_ln);

    // 11) ffh = gelu(ln3 @ Wff1 + bff1), rounded
    tgemm<13><<<ggrid(MX, DFF), 256, GSMEM>>>(
        p_ln, p_w + OW_FF1, bff1, nullptr, p_ff, MX, DFF, Dm, Dm, DFF);

    // 12) out = x2 + ffh @ Wff2 + bff2
    tgemm<3><<<ggrid(MX, Dm), 256, GSMEM>>>(
        p_ff, p_w + OW_FF2, bff2, p_x2, out, MX, Dm, DFF, DFF, Dm);
}